// round 2
// baseline (speedup 1.0000x reference)
#include <cuda_runtime.h>
#include <math.h>

#define B_ 8
#define T_ 2048
#define D_ 2048
#define H_ 128
#define M_ (B_*T_)

// Scratch for q,k,v projections (8 MB each) — __device__ globals per alloc rules.
__device__ float g_q[M_*H_];
__device__ float g_k[M_*H_];
__device__ float g_v[M_*H_];

// ---------------------------------------------------------------------------
// Projection GEMM: out[M,128] = x[M,2048] @ W[2048,128]
// Block tile 128x128, BK=16, 256 threads, 8x8 per thread.
// blockIdx.y selects (Wq->g_q, Wk->g_k, Wv->g_v).
// ---------------------------------------------------------------------------
__global__ __launch_bounds__(256) void proj_kernel(
    const float* __restrict__ x,
    const float* __restrict__ Wq,
    const float* __restrict__ Wk,
    const float* __restrict__ Wv)
{
    __shared__ float As[16][132];   // [k][m] (transposed stage)
    __shared__ float Bs[16][132];   // [k][n]

    const float* W;
    float* out;
    if (blockIdx.y == 0)      { W = Wq; out = g_q; }
    else if (blockIdx.y == 1) { W = Wk; out = g_k; }
    else                      { W = Wv; out = g_v; }

    const int t  = threadIdx.x;
    const int tx = t & 15;       // 16 x 16 thread grid
    const int ty = t >> 4;
    const int m0 = blockIdx.x * 128;

    float acc[8][8];
#pragma unroll
    for (int i = 0; i < 8; i++)
#pragma unroll
        for (int j = 0; j < 8; j++) acc[i][j] = 0.f;

    // A-load: row = t>>1 (0..127), k-offset = (t&1)*8  (two float4 per thread)
    const int ar = t >> 1;
    const int ak = (t & 1) * 8;
    // B-load: k = t>>4 (0..15), n = (t&15)*8
    const int bk = t >> 4;
    const int bn = (t & 15) * 8;

    for (int k0 = 0; k0 < D_; k0 += 16) {
        const float4* ap = (const float4*)(x + (size_t)(m0 + ar) * D_ + k0 + ak);
        float4 a0 = ap[0], a1 = ap[1];
        As[ak+0][ar] = a0.x; As[ak+1][ar] = a0.y; As[ak+2][ar] = a0.z; As[ak+3][ar] = a0.w;
        As[ak+4][ar] = a1.x; As[ak+5][ar] = a1.y; As[ak+6][ar] = a1.z; As[ak+7][ar] = a1.w;

        const float4* bp = (const float4*)(W + (size_t)(k0 + bk) * H_ + bn);
        float4 b0 = bp[0], b1 = bp[1];
        *(float4*)&Bs[bk][bn]     = b0;
        *(float4*)&Bs[bk][bn + 4] = b1;
        __syncthreads();

#pragma unroll
        for (int kk = 0; kk < 16; kk++) {
            float a[8], b[8];
            float4 ta0 = *(const float4*)&As[kk][ty*8];
            float4 ta1 = *(const float4*)&As[kk][ty*8 + 4];
            a[0]=ta0.x; a[1]=ta0.y; a[2]=ta0.z; a[3]=ta0.w;
            a[4]=ta1.x; a[5]=ta1.y; a[6]=ta1.z; a[7]=ta1.w;
            float4 tb0 = *(const float4*)&Bs[kk][tx*8];
            float4 tb1 = *(const float4*)&Bs[kk][tx*8 + 4];
            b[0]=tb0.x; b[1]=tb0.y; b[2]=tb0.z; b[3]=tb0.w;
            b[4]=tb1.x; b[5]=tb1.y; b[6]=tb1.z; b[7]=tb1.w;
#pragma unroll
            for (int i = 0; i < 8; i++)
#pragma unroll
                for (int j = 0; j < 8; j++)
                    acc[i][j] = fmaf(a[i], b[j], acc[i][j]);
        }
        __syncthreads();
    }

#pragma unroll
    for (int i = 0; i < 8; i++) {
        float* op = out + (size_t)(m0 + ty*8 + i) * H_ + tx*8;
        float4 v0 = make_float4(acc[i][0], acc[i][1], acc[i][2], acc[i][3]);
        float4 v1 = make_float4(acc[i][4], acc[i][5], acc[i][6], acc[i][7]);
        *(float4*)(op)     = v0;
        *(float4*)(op + 4) = v1;
    }
}

// ---------------------------------------------------------------------------
// Flash attention, fp32. BM=BN=64, head dim 128 resident.
// Grid: (T/BM, B). 256 threads. Online softmax (m,l in smem).
// ---------------------------------------------------------------------------
#define BM 64
#define BN 64
#define TSTR 132        // Q/K/V smem stride (floats): float4-aligned, low conflict
#define PSTR 65         // P smem stride: conflict-free row reads

#define SM_FLOATS (3*64*TSTR + 64*PSTR + 64*3 + 256)

__global__ __launch_bounds__(256) void flash_kernel(float* __restrict__ out)
{
    extern __shared__ float sm[];
    float* Qs   = sm;                    // [64][132]
    float* Ks   = Qs  + 64*TSTR;         // [64][132]
    float* Vs   = Ks  + 64*TSTR;         // [64][132]
    float* Ps   = Vs  + 64*TSTR;         // [64][65]
    float* m_s  = Ps  + 64*PSTR;         // [64]
    float* l_s  = m_s + 64;              // [64]
    float* sc_s = l_s + 64;              // [64]
    float* psum = sc_s + 64;             // [4][64]

    const int t  = threadIdx.x;
    // Biggest q-blocks first for wave balance under the causal triangle.
    const int qb = (int)gridDim.x - 1 - (int)blockIdx.x;
    const int b  = blockIdx.y;
    const int q0 = qb * BM;
    const size_t base = (size_t)b * T_ * H_;

    const int lr  = t >> 2;              // tile-load row 0..63
    const int ld0 = (t & 3) * 32;        // tile-load d offset

    // Load Q tile (row-major, float4)
    {
        const float4* src = (const float4*)(g_q + base + (size_t)(q0 + lr) * H_ + ld0);
        float4* dst = (float4*)&Qs[lr*TSTR + ld0];
#pragma unroll
        for (int w = 0; w < 8; w++) dst[w] = src[w];
    }
    if (t < BM) { m_s[t] = -1e30f; l_s[t] = 0.f; }

    const int tx  = t & 15;              // S-phase 16x16 grid
    const int ty  = t >> 4;
    const int pr  = t & 63;              // PV/output row
    const int pd0 = (t >> 6) * 32;       // PV/output d offset

    float acc[32];
#pragma unroll
    for (int i = 0; i < 32; i++) acc[i] = 0.f;

    const float RS = 11.313708498984761f;   // sqrt(128) (faithful to source)

    for (int kb = 0; kb <= qb; kb++) {
        const int k0 = kb * BN;
        __syncthreads();   // protect K/V/P reuse from previous iteration's readers

        // Load K,V tiles
        {
            const float4* ks = (const float4*)(g_k + base + (size_t)(k0 + lr) * H_ + ld0);
            const float4* vs = (const float4*)(g_v + base + (size_t)(k0 + lr) * H_ + ld0);
            float4* kd = (float4*)&Ks[lr*TSTR + ld0];
            float4* vd = (float4*)&Vs[lr*TSTR + ld0];
#pragma unroll
            for (int w = 0; w < 8; w++) { kd[w] = ks[w]; vd[w] = vs[w]; }
        }
        __syncthreads();

        // S = Q K^T  (4x4 per thread, float4 over d)
        float s[4][4];
#pragma unroll
        for (int i = 0; i < 4; i++)
#pragma unroll
            for (int j = 0; j < 4; j++) s[i][j] = 0.f;

        for (int d0 = 0; d0 < H_; d0 += 4) {
            float4 a4[4], b4[4];
#pragma unroll
            for (int i = 0; i < 4; i++)
                a4[i] = *(const float4*)&Qs[(ty*4 + i)*TSTR + d0];
#pragma unroll
            for (int j = 0; j < 4; j++)
                b4[j] = *(const float4*)&Ks[(tx*4 + j)*TSTR + d0];
#pragma unroll
            for (int i = 0; i < 4; i++)
#pragma unroll
                for (int j = 0; j < 4; j++) {
                    s[i][j] = fmaf(a4[i].x, b4[j].x, s[i][j]);
                    s[i][j] = fmaf(a4[i].y, b4[j].y, s[i][j]);
                    s[i][j] = fmaf(a4[i].z, b4[j].z, s[i][j]);
                    s[i][j] = fmaf(a4[i].w, b4[j].w, s[i][j]);
                }
        }

        // scale + causal mask + stage to Ps
#pragma unroll
        for (int i = 0; i < 4; i++) {
            const int qr = q0 + ty*4 + i;
#pragma unroll
            for (int j = 0; j < 4; j++) {
                const int kc = k0 + tx*4 + j;
                Ps[(ty*4 + i)*PSTR + tx*4 + j] =
                    (kc <= qr) ? s[i][j] * RS : -1e9f;
            }
        }
        __syncthreads();

        // softmax phase 1: per-row max + rescale factor (64 threads)
        if (t < BM) {
            float mx = -1e30f;
#pragma unroll 8
            for (int j = 0; j < BN; j++) mx = fmaxf(mx, Ps[t*PSTR + j]);
            const float m_old = m_s[t];
            const float m_new = fmaxf(m_old, mx);
            m_s[t]  = m_new;
            sc_s[t] = __expf(m_old - m_new);
        }
        __syncthreads();

        // phase 2: exponentiate (all 256 threads, 16 cols each) + partial sums
        {
            const float mrow = m_s[pr];
            const int j0 = (t >> 6) * 16;
            float ps = 0.f;
#pragma unroll
            for (int j = j0; j < j0 + 16; j++) {
                const float e = __expf(Ps[pr*PSTR + j] - mrow);
                Ps[pr*PSTR + j] = e;
                ps += e;
            }
            psum[(t >> 6)*64 + pr] = ps;
        }
        __syncthreads();

        // phase 3: update l (64 threads) — others proceed to PV (no race on l_s)
        if (t < BM)
            l_s[t] = l_s[t]*sc_s[t] + psum[t] + psum[64+t] + psum[128+t] + psum[192+t];

        // rescale accumulators, then acc += P @ V
        const float scv = sc_s[pr];
#pragma unroll
        for (int i = 0; i < 32; i++) acc[i] *= scv;

        for (int j = 0; j < BN; j++) {
            const float p = Ps[pr*PSTR + j];
            const float4* vr = (const float4*)&Vs[j*TSTR + pd0];
#pragma unroll
            for (int w = 0; w < 8; w++) {
                const float4 vv = vr[w];
                acc[w*4+0] = fmaf(p, vv.x, acc[w*4+0]);
                acc[w*4+1] = fmaf(p, vv.y, acc[w*4+1]);
                acc[w*4+2] = fmaf(p, vv.z, acc[w*4+2]);
                acc[w*4+3] = fmaf(p, vv.w, acc[w*4+3]);
            }
        }
    }

    __syncthreads();   // l_s final
    const float linv = 1.f / l_s[pr];
    float* op = out + base + (size_t)(q0 + pr) * H_ + pd0;
#pragma unroll
    for (int w = 0; w < 8; w++) {
        float4 v = make_float4(acc[w*4+0]*linv, acc[w*4+1]*linv,
                               acc[w*4+2]*linv, acc[w*4+3]*linv);
        *(float4*)(op + w*4) = v;
    }
}

// ---------------------------------------------------------------------------
extern "C" void kernel_launch(void* const* d_in, const int* in_sizes, int n_in,
                              void* d_out, int out_size)
{
    (void)in_sizes; (void)n_in; (void)out_size;
    const float* x  = (const float*)d_in[0];
    const float* Wq = (const float*)d_in[1];
    const float* Wk = (const float*)d_in[2];
    const float* Wv = (const float*)d_in[3];
    float* out = (float*)d_out;

    // Projections: grid (M/128, 3)
    dim3 pgrid(M_ / 128, 3);
    proj_kernel<<<pgrid, 256>>>(x, Wq, Wk, Wv);

    // Flash attention
    static const size_t smem = SM_FLOATS * sizeof(float);
    cudaFuncSetAttribute(flash_kernel,
                         cudaFuncAttributeMaxDynamicSharedMemorySize, (int)smem);
    dim3 fgrid(T_ / BM, B_);
    flash_kernel<<<fgrid, 256, smem>>>(out);
}

// round 5
// speedup vs baseline: 1.4310x; 1.4310x over previous
#include <cuda_runtime.h>
#include <math.h>

#define B_ 8
#define T_ 2048
#define D_ 2048
#define H_ 128
#define M_ (B_*T_)

// Scratch for q,k,v projections — __device__ globals per alloc rules.
__device__ float g_q[M_*H_];
__device__ float g_k[M_*H_];
__device__ float g_v[M_*H_];

// ---------------------------------------------------------------------------
// Projection GEMM (unchanged — at fp32 FFMA roofline):
// out[M,128] = x[M,2048] @ W[2048,128], 128x128 tile, BK=16, 256 thr, 8x8/thr
// ---------------------------------------------------------------------------
__global__ __launch_bounds__(256) void proj_kernel(
    const float* __restrict__ x,
    const float* __restrict__ Wq,
    const float* __restrict__ Wk,
    const float* __restrict__ Wv)
{
    __shared__ float As[16][132];
    __shared__ float Bs[16][132];

    const float* W;
    float* out;
    if (blockIdx.y == 0)      { W = Wq; out = g_q; }
    else if (blockIdx.y == 1) { W = Wk; out = g_k; }
    else                      { W = Wv; out = g_v; }

    const int t  = threadIdx.x;
    const int tx = t & 15;
    const int ty = t >> 4;
    const int m0 = blockIdx.x * 128;

    float acc[8][8];
#pragma unroll
    for (int i = 0; i < 8; i++)
#pragma unroll
        for (int j = 0; j < 8; j++) acc[i][j] = 0.f;

    const int ar = t >> 1;
    const int ak = (t & 1) * 8;
    const int bk = t >> 4;
    const int bn = (t & 15) * 8;

    for (int k0 = 0; k0 < D_; k0 += 16) {
        const float4* ap = (const float4*)(x + (size_t)(m0 + ar) * D_ + k0 + ak);
        float4 a0 = ap[0], a1 = ap[1];
        As[ak+0][ar] = a0.x; As[ak+1][ar] = a0.y; As[ak+2][ar] = a0.z; As[ak+3][ar] = a0.w;
        As[ak+4][ar] = a1.x; As[ak+5][ar] = a1.y; As[ak+6][ar] = a1.z; As[ak+7][ar] = a1.w;

        const float4* bp = (const float4*)(W + (size_t)(k0 + bk) * H_ + bn);
        float4 b0 = bp[0], b1 = bp[1];
        *(float4*)&Bs[bk][bn]     = b0;
        *(float4*)&Bs[bk][bn + 4] = b1;
        __syncthreads();

#pragma unroll
        for (int kk = 0; kk < 16; kk++) {
            float a[8], b[8];
            float4 ta0 = *(const float4*)&As[kk][ty*8];
            float4 ta1 = *(const float4*)&As[kk][ty*8 + 4];
            a[0]=ta0.x; a[1]=ta0.y; a[2]=ta0.z; a[3]=ta0.w;
            a[4]=ta1.x; a[5]=ta1.y; a[6]=ta1.z; a[7]=ta1.w;
            float4 tb0 = *(const float4*)&Bs[kk][tx*8];
            float4 tb1 = *(const float4*)&Bs[kk][tx*8 + 4];
            b[0]=tb0.x; b[1]=tb0.y; b[2]=tb0.z; b[3]=tb0.w;
            b[4]=tb1.x; b[5]=tb1.y; b[6]=tb1.z; b[7]=tb1.w;
#pragma unroll
            for (int i = 0; i < 8; i++)
#pragma unroll
                for (int j = 0; j < 8; j++)
                    acc[i][j] = fmaf(a[i], b[j], acc[i][j]);
        }
        __syncthreads();
    }

#pragma unroll
    for (int i = 0; i < 8; i++) {
        float* op = out + (size_t)(m0 + ty*8 + i) * H_ + tx*8;
        *(float4*)(op)     = make_float4(acc[i][0], acc[i][1], acc[i][2], acc[i][3]);
        *(float4*)(op + 4) = make_float4(acc[i][4], acc[i][5], acc[i][6], acc[i][7]);
    }
}

// ---------------------------------------------------------------------------
// Flash attention v2: BM=BN=64, 256 threads.
// Q,K staged transposed [d][m]; P row-major; m/l register-resident with
// width-16 shuffle reductions. CTA processes q-block pair (31-p, p): uniform
// 33 tile-iterations per CTA, 128 CTAs, single balanced wave.
// ---------------------------------------------------------------------------
#define BM 64
#define BN 64
#define VSTR 132
#define PSTR 68

#define SM2_FLOATS (128*64 + 128*64 + 64*VSTR + 64*PSTR)

__global__ __launch_bounds__(256) void flash2_kernel(float* __restrict__ out)
{
    extern __shared__ float sm[];
    float* QT = sm;                 // [128 d][64 m]
    float* KT = QT + 128*64;        // [128 d][64 n]
    float* Vs = KT + 128*64;        // [64 n][VSTR]
    float* Ps = Vs + 64*VSTR;       // [64 m][PSTR]

    const int t  = threadIdx.x;
    const int tx = t & 15;
    const int ty = t >> 4;
    const int b  = blockIdx.y;
    const size_t base = (size_t)b * T_ * H_;

    // staging ids: row within tile + 32-float d chunk
    const int sn  = t & 63;
    const int sd0 = (t >> 6) * 32;

    const float RS = 11.313708498984761f;   // sqrt(128), faithful to source

    for (int pass = 0; pass < 2; pass++) {
        const int qb = (pass == 0) ? (31 - (int)blockIdx.x) : (int)blockIdx.x;
        const int q0 = qb * BM;

        __syncthreads();   // previous pass finished reading smem

        // Stage Q^T (scalar transposed stores: bank = m -> conflict-free)
        {
            const float* src = g_q + base + (size_t)(q0 + sn) * H_ + sd0;
#pragma unroll
            for (int w = 0; w < 8; w++) {
                float4 v = *(const float4*)(src + w*4);
                QT[(sd0 + w*4 + 0)*64 + sn] = v.x;
                QT[(sd0 + w*4 + 1)*64 + sn] = v.y;
                QT[(sd0 + w*4 + 2)*64 + sn] = v.z;
                QT[(sd0 + w*4 + 3)*64 + sn] = v.w;
            }
        }

        float m_run[4], l_run[4], acc[4][8];
#pragma unroll
        for (int i = 0; i < 4; i++) {
            m_run[i] = -1e30f; l_run[i] = 0.f;
#pragma unroll
            for (int c = 0; c < 8; c++) acc[i][c] = 0.f;
        }

        for (int kb = 0; kb <= qb; kb++) {
            const int k0 = kb * BN;
            __syncthreads();   // prior PV done reading KT/Vs/Ps (also covers QT staging)

            // Stage K^T + V
            {
                const float* ks = g_k + base + (size_t)(k0 + sn) * H_ + sd0;
                const float* vs = g_v + base + (size_t)(k0 + sn) * H_ + sd0;
#pragma unroll
                for (int w = 0; w < 8; w++) {
                    float4 kv = *(const float4*)(ks + w*4);
                    KT[(sd0 + w*4 + 0)*64 + sn] = kv.x;
                    KT[(sd0 + w*4 + 1)*64 + sn] = kv.y;
                    KT[(sd0 + w*4 + 2)*64 + sn] = kv.z;
                    KT[(sd0 + w*4 + 3)*64 + sn] = kv.w;
                    *(float4*)&Vs[sn*VSTR + sd0 + w*4] = *(const float4*)(vs + w*4);
                }
            }
            __syncthreads();

            // ---- S = Q K^T : 4x4 per thread, rows 4ty+i, cols 4tx+j ----
            float s[4][4];
#pragma unroll
            for (int i = 0; i < 4; i++)
#pragma unroll
                for (int j = 0; j < 4; j++) s[i][j] = 0.f;

#pragma unroll 8
            for (int kk = 0; kk < H_; kk++) {
                float4 a = *(const float4*)&QT[kk*64 + 4*ty];
                float4 bb = *(const float4*)&KT[kk*64 + 4*tx];
                float av[4] = {a.x, a.y, a.z, a.w};
                float bv[4] = {bb.x, bb.y, bb.z, bb.w};
#pragma unroll
                for (int i = 0; i < 4; i++)
#pragma unroll
                    for (int j = 0; j < 4; j++)
                        s[i][j] = fmaf(av[i], bv[j], s[i][j]);
            }

            // scale + causal mask (diagonal block only)
            if (kb == qb) {
#pragma unroll
                for (int i = 0; i < 4; i++)
#pragma unroll
                    for (int j = 0; j < 4; j++)
                        s[i][j] = (4*tx + j <= 4*ty + i) ? s[i][j]*RS : -1e9f;
            } else {
#pragma unroll
                for (int i = 0; i < 4; i++)
#pragma unroll
                    for (int j = 0; j < 4; j++)
                        s[i][j] *= RS;
            }

            // ---- online softmax, register-resident (width-16 shuffles) ----
            float mnew[4], sc[4];
#pragma unroll
            for (int i = 0; i < 4; i++) {
                float mx = fmaxf(fmaxf(s[i][0], s[i][1]), fmaxf(s[i][2], s[i][3]));
#pragma unroll
                for (int off = 8; off >= 1; off >>= 1)
                    mx = fmaxf(mx, __shfl_xor_sync(0xffffffffu, mx, off, 16));
                mnew[i] = fmaxf(m_run[i], mx);
                sc[i]   = __expf(m_run[i] - mnew[i]);
                m_run[i] = mnew[i];
            }

#pragma unroll
            for (int i = 0; i < 4; i++) {
                float p0 = __expf(s[i][0] - mnew[i]);
                float p1 = __expf(s[i][1] - mnew[i]);
                float p2 = __expf(s[i][2] - mnew[i]);
                float p3 = __expf(s[i][3] - mnew[i]);
                float rs = (p0 + p1) + (p2 + p3);
#pragma unroll
                for (int off = 8; off >= 1; off >>= 1)
                    rs += __shfl_xor_sync(0xffffffffu, rs, off, 16);
                l_run[i] = l_run[i]*sc[i] + rs;
                *(float4*)&Ps[(4*ty + i)*PSTR + 4*tx] = make_float4(p0, p1, p2, p3);
#pragma unroll
                for (int c = 0; c < 8; c++) acc[i][c] *= sc[i];
            }
            __syncthreads();

            // ---- acc += P @ V : rows 4ty+i, cols 8tx+c ----
#pragma unroll 4
            for (int j = 0; j < BN; j++) {
                float pj[4];
#pragma unroll
                for (int i = 0; i < 4; i++)
                    pj[i] = Ps[(4*ty + i)*PSTR + j];      // broadcast across tx
                float4 v0 = *(const float4*)&Vs[j*VSTR + 8*tx];
                float4 v1 = *(const float4*)&Vs[j*VSTR + 8*tx + 4];
                float vv[8] = {v0.x, v0.y, v0.z, v0.w, v1.x, v1.y, v1.z, v1.w};
#pragma unroll
                for (int i = 0; i < 4; i++)
#pragma unroll
                    for (int c = 0; c < 8; c++)
                        acc[i][c] = fmaf(pj[i], vv[c], acc[i][c]);
            }
        }

        // ---- output (all state register-resident; no barrier needed) ----
#pragma unroll
        for (int i = 0; i < 4; i++) {
            const float linv = 1.f / l_run[i];
            float* op = out + base + (size_t)(q0 + 4*ty + i) * H_ + 8*tx;
            *(float4*)(op)     = make_float4(acc[i][0]*linv, acc[i][1]*linv,
                                             acc[i][2]*linv, acc[i][3]*linv);
            *(float4*)(op + 4) = make_float4(acc[i][4]*linv, acc[i][5]*linv,
                                             acc[i][6]*linv, acc[i][7]*linv);
        }
    }
}

// ---------------------------------------------------------------------------
extern "C" void kernel_launch(void* const* d_in, const int* in_sizes, int n_in,
                              void* d_out, int out_size)
{
    (void)in_sizes; (void)n_in; (void)out_size;
    const float* x  = (const float*)d_in[0];
    const float* Wq = (const float*)d_in[1];
    const float* Wk = (const float*)d_in[2];
    const float* Wv = (const float*)d_in[3];
    float* out = (float*)d_out;

    dim3 pgrid(M_ / 128, 3);
    proj_kernel<<<pgrid, 256>>>(x, Wq, Wk, Wv);

    static const size_t smem = SM2_FLOATS * sizeof(float);
    cudaFuncSetAttribute(flash2_kernel,
                         cudaFuncAttributeMaxDynamicSharedMemorySize, (int)smem);
    dim3 fgrid(16, B_);   // 16 block-pairs x 8 batches = 128 balanced CTAs
    flash2_kernel<<<fgrid, 256, smem>>>(out);
}

// round 7
// speedup vs baseline: 2.1270x; 1.4864x over previous
#include <cuda_runtime.h>
#include <cuda_bf16.h>
#include <math.h>
#include <stdint.h>

#define B_ 8
#define T_ 2048
#define D_ 2048
#define H_ 128
#define M_ (B_*T_)

// Scratch (alloc-free rules: __device__ globals)
__device__ float g_q[M_*H_];
__device__ float g_k[M_*H_];
__device__ float g_v[M_*H_];
__device__ __nv_bfloat16 g_wthi[3][H_*D_];   // W^T: [n][k]
__device__ __nv_bfloat16 g_wtlo[3][H_*D_];

// ---------------------------------------------------------------------------
// W convert: split each fp32 weight into bf16 hi + lo, stored transposed [n][k]
// ---------------------------------------------------------------------------
__global__ __launch_bounds__(256) void convert_w_kernel(
    const float* __restrict__ Wq, const float* __restrict__ Wk, const float* __restrict__ Wv)
{
    const int w = blockIdx.y;
    const float* W = (w == 0) ? Wq : (w == 1) ? Wk : Wv;
    const int e = blockIdx.x * 256 + threadIdx.x;    // over 2048*128
    const int k = e >> 7, n = e & 127;
    float v = W[(size_t)k * H_ + n];
    __nv_bfloat16 h = __float2bfloat16(v);
    __nv_bfloat16 l = __float2bfloat16(v - __bfloat162float(h));
    g_wthi[w][(size_t)n * D_ + k] = h;
    g_wtlo[w][(size_t)n * D_ + k] = l;
}

// ---------------------------------------------------------------------------
// Projection via mma.sync (HMMA bf16, fp32 accum), split-compensated:
//   out = x_hi*W_hi + x_hi*W_lo + x_lo*W_hi
// CTA: 128x128 tile for one weight. 8 warps = 2(M) x 4(N); warp = 64x32.
// BK=32. smem row stride 40 elems (80B): 16B-aligned, ldmatrix conflict-free.
// ---------------------------------------------------------------------------
#define BKC 32
#define ASTR 40

__device__ __forceinline__ void ldmat4(uint32_t* r, uint32_t addr) {
    asm volatile("ldmatrix.sync.aligned.m8n8.x4.shared.b16 {%0,%1,%2,%3}, [%4];"
        : "=r"(r[0]), "=r"(r[1]), "=r"(r[2]), "=r"(r[3]) : "r"(addr));
}
__device__ __forceinline__ void mma16816(float* d, const uint32_t* a,
                                         uint32_t b0, uint32_t b1) {
    asm volatile(
        "mma.sync.aligned.m16n8k16.row.col.f32.bf16.bf16.f32 "
        "{%0,%1,%2,%3}, {%4,%5,%6,%7}, {%8,%9}, {%0,%1,%2,%3};"
        : "+f"(d[0]), "+f"(d[1]), "+f"(d[2]), "+f"(d[3])
        : "r"(a[0]), "r"(a[1]), "r"(a[2]), "r"(a[3]), "r"(b0), "r"(b1));
}
__device__ __forceinline__ uint32_t smem_u32(const void* p) {
    uint32_t a;
    asm("{ .reg .u64 t; cvta.to.shared.u64 t, %1; cvt.u32.u64 %0, t; }" : "=r"(a) : "l"(p));
    return a;
}

__global__ __launch_bounds__(256, 2) void proj_hmma_kernel(const float* __restrict__ x)
{
    __shared__ __nv_bfloat16 As_hi[128][ASTR];
    __shared__ __nv_bfloat16 As_lo[128][ASTR];
    __shared__ __nv_bfloat16 Bs_hi[128][ASTR];
    __shared__ __nv_bfloat16 Bs_lo[128][ASTR];

    const int t    = threadIdx.x;
    const int lane = t & 31;
    const int wid  = t >> 5;
    const int wm   = wid & 1;        // M half: 0/1 -> rows wm*64
    const int wn   = wid >> 1;       // N quarter: 0..3 -> cols wn*32
    const int m0   = blockIdx.x * 128;
    const int w    = blockIdx.y;

    const __nv_bfloat16* WT_hi = g_wthi[w];
    const __nv_bfloat16* WT_lo = g_wtlo[w];
    float* out = (w == 0) ? g_q : (w == 1) ? g_k : g_v;

    float acc[4][4][4];
#pragma unroll
    for (int mt = 0; mt < 4; mt++)
#pragma unroll
        for (int nt = 0; nt < 4; nt++)
#pragma unroll
            for (int d = 0; d < 4; d++) acc[mt][nt][d] = 0.f;

    const uint32_t sAhi = smem_u32(&As_hi[0][0]);
    const uint32_t sAlo = smem_u32(&As_lo[0][0]);
    const uint32_t sBhi = smem_u32(&Bs_hi[0][0]);
    const uint32_t sBlo = smem_u32(&Bs_lo[0][0]);

    // per-thread ldmatrix address components (bytes)
    // A: row = wm*64 + mt*16 + (lane&15), col = ks*16 + (lane>>4)*8
    const uint32_t aRow = (uint32_t)(wm*64 + (lane & 15));
    const uint32_t aCol = (uint32_t)((lane >> 4) * 8);
    // B: row = wn*32 + np*16 + (lane&7) + ((lane>>4)&1)*8, col = ks*16 + ((lane>>3)&1)*8
    const uint32_t bRow = (uint32_t)(wn*32 + (lane & 7) + ((lane >> 4) & 1) * 8);
    const uint32_t bCol = (uint32_t)(((lane >> 3) & 1) * 8);

    for (int ch = 0; ch < D_/BKC; ch++) {
        const int k0 = ch * BKC;
        __syncthreads();   // prior compute done reading smem

        // ---- stage A: read x fp32, split to hi/lo bf16 inline ----
#pragma unroll
        for (int i = 0; i < 4; i++) {
            const int pos = t + i*256;          // 0..1023
            const int row = pos >> 3;           // 0..127
            const int c   = pos & 7;            // float4 index (col = c*4)
            float4 v = *(const float4*)(x + (size_t)(m0 + row) * D_ + k0 + c*4);
            __nv_bfloat16 h0 = __float2bfloat16(v.x), h1 = __float2bfloat16(v.y);
            __nv_bfloat16 h2 = __float2bfloat16(v.z), h3 = __float2bfloat16(v.w);
            __nv_bfloat16 l0 = __float2bfloat16(v.x - __bfloat162float(h0));
            __nv_bfloat16 l1 = __float2bfloat16(v.y - __bfloat162float(h1));
            __nv_bfloat16 l2 = __float2bfloat16(v.z - __bfloat162float(h2));
            __nv_bfloat16 l3 = __float2bfloat16(v.w - __bfloat162float(h3));
            *(__nv_bfloat162*)&As_hi[row][c*4]     = __nv_bfloat162(h0, h1);
            *(__nv_bfloat162*)&As_hi[row][c*4 + 2] = __nv_bfloat162(h2, h3);
            *(__nv_bfloat162*)&As_lo[row][c*4]     = __nv_bfloat162(l0, l1);
            *(__nv_bfloat162*)&As_lo[row][c*4 + 2] = __nv_bfloat162(l2, l3);
        }
        // ---- stage B: bf16 hi/lo straight copies (uint4) ----
#pragma unroll
        for (int i = 0; i < 2; i++) {
            const int pos = t + i*256;          // 0..511
            const int row = pos >> 2;           // 0..127
            const int c4  = pos & 3;            // 8-elem group (col = c4*8)
            const size_t goff = (size_t)row * D_ + k0 + c4*8;
            *(uint4*)&Bs_hi[row][c4*8] = *(const uint4*)(WT_hi + goff);
            *(uint4*)&Bs_lo[row][c4*8] = *(const uint4*)(WT_lo + goff);
        }
        __syncthreads();

        // ---- compute: 2 k-steps x 3 products (A frags shared by hh/hl) ----
#pragma unroll
        for (int ks = 0; ks < 2; ks++) {
            const uint32_t aoff = (aRow * ASTR + (uint32_t)(ks*16) + aCol) * 2u;
            const uint32_t boff = (bRow * ASTR + (uint32_t)(ks*16) + bCol) * 2u;

            uint32_t a[4][4], bh[2][4], bl[2][4];
#pragma unroll
            for (int mt = 0; mt < 4; mt++)
                ldmat4(a[mt], sAhi + aoff + (uint32_t)(mt*16*ASTR*2));
#pragma unroll
            for (int np = 0; np < 2; np++) {
                ldmat4(bh[np], sBhi + boff + (uint32_t)(np*16*ASTR*2));
                ldmat4(bl[np], sBlo + boff + (uint32_t)(np*16*ASTR*2));
            }
            // hh
#pragma unroll
            for (int mt = 0; mt < 4; mt++)
#pragma unroll
                for (int nt = 0; nt < 4; nt++)
                    mma16816(acc[mt][nt], a[mt], bh[nt>>1][(nt&1)*2], bh[nt>>1][(nt&1)*2+1]);
            // hl
#pragma unroll
            for (int mt = 0; mt < 4; mt++)
#pragma unroll
                for (int nt = 0; nt < 4; nt++)
                    mma16816(acc[mt][nt], a[mt], bl[nt>>1][(nt&1)*2], bl[nt>>1][(nt&1)*2+1]);
            // lh (reload A as lo)
#pragma unroll
            for (int mt = 0; mt < 4; mt++)
                ldmat4(a[mt], sAlo + aoff + (uint32_t)(mt*16*ASTR*2));
#pragma unroll
            for (int mt = 0; mt < 4; mt++)
#pragma unroll
                for (int nt = 0; nt < 4; nt++)
                    mma16816(acc[mt][nt], a[mt], bh[nt>>1][(nt&1)*2], bh[nt>>1][(nt&1)*2+1]);
        }
    }

    // ---- epilogue: D frag -> gmem (float2 stores, rows l/4 and l/4+8) ----
    const int dr = lane >> 2;
    const int dc = (lane & 3) * 2;
#pragma unroll
    for (int mt = 0; mt < 4; mt++) {
#pragma unroll
        for (int nt = 0; nt < 4; nt++) {
            const int row = m0 + wm*64 + mt*16 + dr;
            const int col = wn*32 + nt*8 + dc;
            *(float2*)&out[(size_t)row * H_ + col] =
                make_float2(acc[mt][nt][0], acc[mt][nt][1]);
            *(float2*)&out[(size_t)(row + 8) * H_ + col] =
                make_float2(acc[mt][nt][2], acc[mt][nt][3]);
        }
    }
}

// ---------------------------------------------------------------------------
// Flash attention (unchanged — 419 µs)
// ---------------------------------------------------------------------------
#define BM 64
#define BN 64
#define VSTR 132
#define PSTR 68
#define SM2_FLOATS (128*64 + 128*64 + 64*VSTR + 64*PSTR)

__global__ __launch_bounds__(256) void flash2_kernel(float* __restrict__ out)
{
    extern __shared__ float sm[];
    float* QT = sm;
    float* KT = QT + 128*64;
    float* Vs = KT + 128*64;
    float* Ps = Vs + 64*VSTR;

    const int t  = threadIdx.x;
    const int tx = t & 15;
    const int ty = t >> 4;
    const int b  = blockIdx.y;
    const size_t base = (size_t)b * T_ * H_;

    const int sn  = t & 63;
    const int sd0 = (t >> 6) * 32;
    const float RS = 11.313708498984761f;

    for (int pass = 0; pass < 2; pass++) {
        const int qb = (pass == 0) ? (31 - (int)blockIdx.x) : (int)blockIdx.x;
        const int q0 = qb * BM;

        __syncthreads();
        {
            const float* src = g_q + base + (size_t)(q0 + sn) * H_ + sd0;
#pragma unroll
            for (int w = 0; w < 8; w++) {
                float4 v = *(const float4*)(src + w*4);
                QT[(sd0 + w*4 + 0)*64 + sn] = v.x;
                QT[(sd0 + w*4 + 1)*64 + sn] = v.y;
                QT[(sd0 + w*4 + 2)*64 + sn] = v.z;
                QT[(sd0 + w*4 + 3)*64 + sn] = v.w;
            }
        }

        float m_run[4], l_run[4], acc[4][8];
#pragma unroll
        for (int i = 0; i < 4; i++) {
            m_run[i] = -1e30f; l_run[i] = 0.f;
#pragma unroll
            for (int c = 0; c < 8; c++) acc[i][c] = 0.f;
        }

        for (int kb = 0; kb <= qb; kb++) {
            const int k0 = kb * BN;
            __syncthreads();
            {
                const float* ks = g_k + base + (size_t)(k0 + sn) * H_ + sd0;
                const float* vs = g_v + base + (size_t)(k0 + sn) * H_ + sd0;
#pragma unroll
                for (int w = 0; w < 8; w++) {
                    float4 kv = *(const float4*)(ks + w*4);
                    KT[(sd0 + w*4 + 0)*64 + sn] = kv.x;
                    KT[(sd0 + w*4 + 1)*64 + sn] = kv.y;
                    KT[(sd0 + w*4 + 2)*64 + sn] = kv.z;
                    KT[(sd0 + w*4 + 3)*64 + sn] = kv.w;
                    *(float4*)&Vs[sn*VSTR + sd0 + w*4] = *(const float4*)(vs + w*4);
                }
            }
            __syncthreads();

            float s[4][4];
#pragma unroll
            for (int i = 0; i < 4; i++)
#pragma unroll
                for (int j = 0; j < 4; j++) s[i][j] = 0.f;

#pragma unroll 8
            for (int kk = 0; kk < H_; kk++) {
                float4 a = *(const float4*)&QT[kk*64 + 4*ty];
                float4 bb = *(const float4*)&KT[kk*64 + 4*tx];
                float av[4] = {a.x, a.y, a.z, a.w};
                float bv[4] = {bb.x, bb.y, bb.z, bb.w};
#pragma unroll
                for (int i = 0; i < 4; i++)
#pragma unroll
                    for (int j = 0; j < 4; j++)
                        s[i][j] = fmaf(av[i], bv[j], s[i][j]);
            }

            if (kb == qb) {
#pragma unroll
                for (int i = 0; i < 4; i++)
#pragma unroll
                    for (int j = 0; j < 4; j++)
                        s[i][j] = (4*tx + j <= 4*ty + i) ? s[i][j]*RS : -1e9f;
            } else {
#pragma unroll
                for (int i = 0; i < 4; i++)
#pragma unroll
                    for (int j = 0; j < 4; j++)
                        s[i][j] *= RS;
            }

            float mnew[4], sc[4];
#pragma unroll
            for (int i = 0; i < 4; i++) {
                float mx = fmaxf(fmaxf(s[i][0], s[i][1]), fmaxf(s[i][2], s[i][3]));
#pragma unroll
                for (int off = 8; off >= 1; off >>= 1)
                    mx = fmaxf(mx, __shfl_xor_sync(0xffffffffu, mx, off, 16));
                mnew[i] = fmaxf(m_run[i], mx);
                sc[i]   = __expf(m_run[i] - mnew[i]);
                m_run[i] = mnew[i];
            }

#pragma unroll
            for (int i = 0; i < 4; i++) {
                float p0 = __expf(s[i][0] - mnew[i]);
                float p1 = __expf(s[i][1] - mnew[i]);
                float p2 = __expf(s[i][2] - mnew[i]);
                float p3 = __expf(s[i][3] - mnew[i]);
                float rs = (p0 + p1) + (p2 + p3);
#pragma unroll
                for (int off = 8; off >= 1; off >>= 1)
                    rs += __shfl_xor_sync(0xffffffffu, rs, off, 16);
                l_run[i] = l_run[i]*sc[i] + rs;
                *(float4*)&Ps[(4*ty + i)*PSTR + 4*tx] = make_float4(p0, p1, p2, p3);
#pragma unroll
                for (int c = 0; c < 8; c++) acc[i][c] *= sc[i];
            }
            __syncthreads();

#pragma unroll 4
            for (int j = 0; j < BN; j++) {
                float pj[4];
#pragma unroll
                for (int i = 0; i < 4; i++)
                    pj[i] = Ps[(4*ty + i)*PSTR + j];
                float4 v0 = *(const float4*)&Vs[j*VSTR + 8*tx];
                float4 v1 = *(const float4*)&Vs[j*VSTR + 8*tx + 4];
                float vv[8] = {v0.x, v0.y, v0.z, v0.w, v1.x, v1.y, v1.z, v1.w};
#pragma unroll
                for (int i = 0; i < 4; i++)
#pragma unroll
                    for (int c = 0; c < 8; c++)
                        acc[i][c] = fmaf(pj[i], vv[c], acc[i][c]);
            }
        }

#pragma unroll
        for (int i = 0; i < 4; i++) {
            const float linv = 1.f / l_run[i];
            float* op = out + base + (size_t)(q0 + 4*ty + i) * H_ + 8*tx;
            *(float4*)(op)     = make_float4(acc[i][0]*linv, acc[i][1]*linv,
                                             acc[i][2]*linv, acc[i][3]*linv);
            *(float4*)(op + 4) = make_float4(acc[i][4]*linv, acc[i][5]*linv,
                                             acc[i][6]*linv, acc[i][7]*linv);
        }
    }
}

// ---------------------------------------------------------------------------
extern "C" void kernel_launch(void* const* d_in, const int* in_sizes, int n_in,
                              void* d_out, int out_size)
{
    (void)in_sizes; (void)n_in; (void)out_size;
    const float* x  = (const float*)d_in[0];
    const float* Wq = (const float*)d_in[1];
    const float* Wk = (const float*)d_in[2];
    const float* Wv = (const float*)d_in[3];
    float* out = (float*)d_out;

    convert_w_kernel<<<dim3((D_*H_)/256, 3), 256>>>(Wq, Wk, Wv);

    proj_hmma_kernel<<<dim3(M_/128, 3), 256>>>(x);

    static const size_t smem = SM2_FLOATS * sizeof(float);
    cudaFuncSetAttribute(flash2_kernel,
                         cudaFuncAttributeMaxDynamicSharedMemorySize, (int)smem);
    flash2_kernel<<<dim3(16, B_), 256, smem>>>(out);
}

// round 10
// speedup vs baseline: 3.5089x; 1.6497x over previous
#include <cuda_runtime.h>
#include <cuda_bf16.h>
#include <math.h>
#include <stdint.h>

#define B_ 8
#define T_ 2048
#define D_ 2048
#define H_ 128
#define M_ (B_*T_)

// Scratch (alloc-free rules: __device__ globals)
__device__ __nv_bfloat16 g_qhi[M_*H_], g_qlo[M_*H_];   // q pre-scaled by sqrt(128)
__device__ __nv_bfloat16 g_khi[M_*H_], g_klo[M_*H_];
__device__ __nv_bfloat16 g_vhi[M_*H_], g_vlo[M_*H_];
__device__ __nv_bfloat16 g_wthi[3][H_*D_];             // W^T: [n][k]
__device__ __nv_bfloat16 g_wtlo[3][H_*D_];

// ---------------------------------------------------------------------------
// helpers
// ---------------------------------------------------------------------------
__device__ __forceinline__ uint32_t smem_u32(const void* p) {
    uint32_t a;
    asm("{ .reg .u64 t; cvta.to.shared.u64 t, %1; cvt.u32.u64 %0, t; }" : "=r"(a) : "l"(p));
    return a;
}
__device__ __forceinline__ void ldmat4(uint32_t* r, uint32_t addr) {
    asm volatile("ldmatrix.sync.aligned.m8n8.x4.shared.b16 {%0,%1,%2,%3}, [%4];"
        : "=r"(r[0]), "=r"(r[1]), "=r"(r[2]), "=r"(r[3]) : "r"(addr));
}
__device__ __forceinline__ void ldmat2t(uint32_t* r, uint32_t addr) {
    asm volatile("ldmatrix.sync.aligned.m8n8.x2.trans.shared.b16 {%0,%1}, [%2];"
        : "=r"(r[0]), "=r"(r[1]) : "r"(addr));
}
__device__ __forceinline__ void mma16816(float* d, const uint32_t* a,
                                         uint32_t b0, uint32_t b1) {
    asm volatile(
        "mma.sync.aligned.m16n8k16.row.col.f32.bf16.bf16.f32 "
        "{%0,%1,%2,%3}, {%4,%5,%6,%7}, {%8,%9}, {%0,%1,%2,%3};"
        : "+f"(d[0]), "+f"(d[1]), "+f"(d[2]), "+f"(d[3])
        : "r"(a[0]), "r"(a[1]), "r"(a[2]), "r"(a[3]), "r"(b0), "r"(b1));
}
__device__ __forceinline__ uint32_t pack_bf16x2(float even, float odd) {
    uint32_t r;
    asm("cvt.rn.bf16x2.f32 %0, %1, %2;" : "=r"(r) : "f"(odd), "f"(even));
    return r;
}

// ---------------------------------------------------------------------------
// W convert (unchanged)
// ---------------------------------------------------------------------------
__global__ __launch_bounds__(256) void convert_w_kernel(
    const float* __restrict__ Wq, const float* __restrict__ Wk, const float* __restrict__ Wv)
{
    const int w = blockIdx.y;
    const float* W = (w == 0) ? Wq : (w == 1) ? Wk : Wv;
    const int e = blockIdx.x * 256 + threadIdx.x;
    const int k = e >> 7, n = e & 127;
    float v = W[(size_t)k * H_ + n];
    __nv_bfloat16 h = __float2bfloat16(v);
    __nv_bfloat16 l = __float2bfloat16(v - __bfloat162float(h));
    g_wthi[w][(size_t)n * D_ + k] = h;
    g_wtlo[w][(size_t)n * D_ + k] = l;
}

// ---------------------------------------------------------------------------
// Projection HMMA (round-7 core; epilogue now emits bf16 hi/lo, q scaled)
// ---------------------------------------------------------------------------
#define BKC 32
#define ASTR 40

__global__ __launch_bounds__(256, 2) void proj_hmma_kernel(const float* __restrict__ x)
{
    __shared__ __nv_bfloat16 As_hi[128][ASTR];
    __shared__ __nv_bfloat16 As_lo[128][ASTR];
    __shared__ __nv_bfloat16 Bs_hi[128][ASTR];
    __shared__ __nv_bfloat16 Bs_lo[128][ASTR];

    const int t    = threadIdx.x;
    const int lane = t & 31;
    const int wid  = t >> 5;
    const int wm   = wid & 1;
    const int wn   = wid >> 1;
    const int m0   = blockIdx.x * 128;
    const int w    = blockIdx.y;

    const __nv_bfloat16* WT_hi = g_wthi[w];
    const __nv_bfloat16* WT_lo = g_wtlo[w];
    __nv_bfloat16* ohi = (w == 0) ? g_qhi : (w == 1) ? g_khi : g_vhi;
    __nv_bfloat16* olo = (w == 0) ? g_qlo : (w == 1) ? g_klo : g_vlo;
    const float oscale = (w == 0) ? 11.313708498984761f : 1.0f;   // sqrt(128) into q

    float acc[4][4][4];
#pragma unroll
    for (int mt = 0; mt < 4; mt++)
#pragma unroll
        for (int nt = 0; nt < 4; nt++)
#pragma unroll
            for (int d = 0; d < 4; d++) acc[mt][nt][d] = 0.f;

    const uint32_t sAhi = smem_u32(&As_hi[0][0]);
    const uint32_t sAlo = smem_u32(&As_lo[0][0]);
    const uint32_t sBhi = smem_u32(&Bs_hi[0][0]);
    const uint32_t sBlo = smem_u32(&Bs_lo[0][0]);

    const uint32_t aRow = (uint32_t)(wm*64 + (lane & 15));
    const uint32_t aCol = (uint32_t)((lane >> 4) * 8);
    const uint32_t bRow = (uint32_t)(wn*32 + (lane & 7) + ((lane >> 4) & 1) * 8);
    const uint32_t bCol = (uint32_t)(((lane >> 3) & 1) * 8);

    for (int ch = 0; ch < D_/BKC; ch++) {
        const int k0 = ch * BKC;
        __syncthreads();

#pragma unroll
        for (int i = 0; i < 4; i++) {
            const int pos = t + i*256;
            const int row = pos >> 3;
            const int c   = pos & 7;
            float4 v = *(const float4*)(x + (size_t)(m0 + row) * D_ + k0 + c*4);
            __nv_bfloat16 h0 = __float2bfloat16(v.x), h1 = __float2bfloat16(v.y);
            __nv_bfloat16 h2 = __float2bfloat16(v.z), h3 = __float2bfloat16(v.w);
            __nv_bfloat16 l0 = __float2bfloat16(v.x - __bfloat162float(h0));
            __nv_bfloat16 l1 = __float2bfloat16(v.y - __bfloat162float(h1));
            __nv_bfloat16 l2 = __float2bfloat16(v.z - __bfloat162float(h2));
            __nv_bfloat16 l3 = __float2bfloat16(v.w - __bfloat162float(h3));
            *(__nv_bfloat162*)&As_hi[row][c*4]     = __nv_bfloat162(h0, h1);
            *(__nv_bfloat162*)&As_hi[row][c*4 + 2] = __nv_bfloat162(h2, h3);
            *(__nv_bfloat162*)&As_lo[row][c*4]     = __nv_bfloat162(l0, l1);
            *(__nv_bfloat162*)&As_lo[row][c*4 + 2] = __nv_bfloat162(l2, l3);
        }
#pragma unroll
        for (int i = 0; i < 2; i++) {
            const int pos = t + i*256;
            const int row = pos >> 2;
            const int c4  = pos & 3;
            const size_t goff = (size_t)row * D_ + k0 + c4*8;
            *(uint4*)&Bs_hi[row][c4*8] = *(const uint4*)(WT_hi + goff);
            *(uint4*)&Bs_lo[row][c4*8] = *(const uint4*)(WT_lo + goff);
        }
        __syncthreads();

#pragma unroll
        for (int ks = 0; ks < 2; ks++) {
            const uint32_t aoff = (aRow * ASTR + (uint32_t)(ks*16) + aCol) * 2u;
            const uint32_t boff = (bRow * ASTR + (uint32_t)(ks*16) + bCol) * 2u;

            uint32_t a[4][4], bh[2][4], bl[2][4];
#pragma unroll
            for (int mt = 0; mt < 4; mt++)
                ldmat4(a[mt], sAhi + aoff + (uint32_t)(mt*16*ASTR*2));
#pragma unroll
            for (int np = 0; np < 2; np++) {
                ldmat4(bh[np], sBhi + boff + (uint32_t)(np*16*ASTR*2));
                ldmat4(bl[np], sBlo + boff + (uint32_t)(np*16*ASTR*2));
            }
#pragma unroll
            for (int mt = 0; mt < 4; mt++)
#pragma unroll
                for (int nt = 0; nt < 4; nt++)
                    mma16816(acc[mt][nt], a[mt], bh[nt>>1][(nt&1)*2], bh[nt>>1][(nt&1)*2+1]);
#pragma unroll
            for (int mt = 0; mt < 4; mt++)
#pragma unroll
                for (int nt = 0; nt < 4; nt++)
                    mma16816(acc[mt][nt], a[mt], bl[nt>>1][(nt&1)*2], bl[nt>>1][(nt&1)*2+1]);
#pragma unroll
            for (int mt = 0; mt < 4; mt++)
                ldmat4(a[mt], sAlo + aoff + (uint32_t)(mt*16*ASTR*2));
#pragma unroll
            for (int mt = 0; mt < 4; mt++)
#pragma unroll
                for (int nt = 0; nt < 4; nt++)
                    mma16816(acc[mt][nt], a[mt], bh[nt>>1][(nt&1)*2], bh[nt>>1][(nt&1)*2+1]);
        }
    }

    // epilogue: split to bf16 hi/lo, store pairs
    const int dr = lane >> 2;
    const int dc = (lane & 3) * 2;
#pragma unroll
    for (int mt = 0; mt < 4; mt++) {
#pragma unroll
        for (int nt = 0; nt < 4; nt++) {
            const int row = m0 + wm*64 + mt*16 + dr;
            const int col = wn*32 + nt*8 + dc;
#pragma unroll
            for (int half = 0; half < 2; half++) {
                const int rr = row + half*8;
                float v0 = acc[mt][nt][half*2 + 0] * oscale;
                float v1 = acc[mt][nt][half*2 + 1] * oscale;
                __nv_bfloat16 h0 = __float2bfloat16(v0);
                __nv_bfloat16 h1 = __float2bfloat16(v1);
                __nv_bfloat16 e0 = __float2bfloat16(v0 - __bfloat162float(h0));
                __nv_bfloat16 e1 = __float2bfloat16(v1 - __bfloat162float(h1));
                *(__nv_bfloat162*)(ohi + (size_t)rr * H_ + col) = __nv_bfloat162(h0, h1);
                *(__nv_bfloat162*)(olo + (size_t)rr * H_ + col) = __nv_bfloat162(e0, e1);
            }
        }
    }
}

// ---------------------------------------------------------------------------
// Flash attention v3 — HMMA, FA2 register dataflow, split-compensated.
// CTA = 2 independent 128-thread groups (named barriers), each BM=64 q rows.
// Group 0: q-block 31-p; group 1: q-block p  -> uniform 33 iters/CTA.
// ---------------------------------------------------------------------------
#define FSTR 136                 // smem row stride in halves (272B, 16B-aligned)
#define FQH  (64*FSTR)           // halves per tile component
#define FGRP (6*FQH)             // halves per group
#define FSMEM (2*FGRP*2)         // bytes total (208896)

__global__ __launch_bounds__(256) void flash3_kernel(float* __restrict__ out)
{
    extern __shared__ __nv_bfloat16 fsm[];
    const int t    = threadIdx.x;
    const int g    = t >> 7;
    const int gt   = t & 127;
    const int warp = gt >> 5;
    const int lane = t & 31;
    const int b    = blockIdx.y;
    const int p    = blockIdx.x;
    const int qb   = g ? p : (31 - p);
    const int q0   = qb * 64;
    const size_t base = (size_t)b * T_ * H_;

    __nv_bfloat16* sQh = fsm + g*FGRP;
    __nv_bfloat16* sQl = sQh + FQH;
    __nv_bfloat16* sKh = sQl + FQH;
    __nv_bfloat16* sKl = sKh + FQH;
    __nv_bfloat16* sVh = sKl + FQH;
    __nv_bfloat16* sVl = sVh + FQH;
    const uint32_t aQh = smem_u32(sQh), aQl = smem_u32(sQl);
    const uint32_t aKh = smem_u32(sKh), aKl = smem_u32(sKl);
    const uint32_t aVh = smem_u32(sVh), aVl = smem_u32(sVl);

    // ---- stage Q (once per group) ----
#pragma unroll
    for (int i = 0; i < 8; i++) {
        const int idx = gt + i*128;
        const int row = idx >> 4, c = idx & 15;
        const size_t go = base + (size_t)(q0 + row)*H_ + c*8;
        *(uint4*)(sQh + row*FSTR + c*8) = *(const uint4*)(g_qhi + go);
        *(uint4*)(sQl + row*FSTR + c*8) = *(const uint4*)(g_qlo + go);
    }

    float o[16][4];
#pragma unroll
    for (int nt = 0; nt < 16; nt++)
#pragma unroll
        for (int e = 0; e < 4; e++) o[nt][e] = 0.f;
    float m0r = -1e30f, m1r = -1e30f, l0r = 0.f, l1r = 0.f;

    // fragment address components (bytes, relative to each component base)
    const uint32_t aoff = (uint32_t)(((warp*16 + (lane & 15))*FSTR + (lane >> 4)*8) * 2);
    const uint32_t boff = (uint32_t)((((lane & 7) + ((lane >> 4) & 1)*8)*FSTR
                                      + ((lane >> 3) & 1)*8) * 2);
    const uint32_t voff = (uint32_t)(((lane & 15)*FSTR) * 2);

    const int r0 = warp*16 + (lane >> 2);      // local q-row (and +8)

    for (int kb = 0; kb <= qb; kb++) {
        const int k0 = kb * 64;
        asm volatile("bar.sync %0, %1;" :: "r"(g+1), "r"(128) : "memory");

        // ---- stage K, V (direct copies, [key][hd]) ----
#pragma unroll
        for (int i = 0; i < 8; i++) {
            const int idx = gt + i*128;
            const int row = idx >> 4, c = idx & 15;
            const size_t go = base + (size_t)(k0 + row)*H_ + c*8;
            *(uint4*)(sKh + row*FSTR + c*8) = *(const uint4*)(g_khi + go);
            *(uint4*)(sKl + row*FSTR + c*8) = *(const uint4*)(g_klo + go);
            *(uint4*)(sVh + row*FSTR + c*8) = *(const uint4*)(g_vhi + go);
            *(uint4*)(sVl + row*FSTR + c*8) = *(const uint4*)(g_vlo + go);
        }
        asm volatile("bar.sync %0, %1;" :: "r"(g+1), "r"(128) : "memory");

        // ---- S = Q K^T : 16x64 per warp, 4 split products ----
        float s[8][4];
#pragma unroll
        for (int nt = 0; nt < 8; nt++)
#pragma unroll
            for (int e = 0; e < 4; e++) s[nt][e] = 0.f;

#pragma unroll
        for (int kc = 0; kc < 8; kc++) {
            uint32_t aH[4], aL[4];
            ldmat4(aH, aQh + aoff + kc*32);
            ldmat4(aL, aQl + aoff + kc*32);
#pragma unroll
            for (int ntp = 0; ntp < 4; ntp++) {
                uint32_t bH[4], bL[4];
                const uint32_t bo = boff + (uint32_t)(ntp*(16*FSTR*2)) + kc*32;
                ldmat4(bH, aKh + bo);
                ldmat4(bL, aKl + bo);
#pragma unroll
                for (int h = 0; h < 2; h++) {
                    const int nt = ntp*2 + h;
                    mma16816(s[nt], aH, bH[2*h], bH[2*h+1]);
                    mma16816(s[nt], aH, bL[2*h], bL[2*h+1]);
                    mma16816(s[nt], aL, bH[2*h], bH[2*h+1]);
                    mma16816(s[nt], aL, bL[2*h], bL[2*h+1]);
                }
            }
        }

        // ---- causal mask (diagonal block only; sqrt(128) pre-folded in q) ----
        if (kb == qb) {
#pragma unroll
            for (int nt = 0; nt < 8; nt++) {
                const int c0 = nt*8 + 2*(lane & 3);
                if (c0     > r0)     s[nt][0] = -1e9f;
                if (c0 + 1 > r0)     s[nt][1] = -1e9f;
                if (c0     > r0 + 8) s[nt][2] = -1e9f;
                if (c0 + 1 > r0 + 8) s[nt][3] = -1e9f;
            }
        }

        // ---- online softmax (rows in quads: shfl xor 1,2) ----
        float mx0 = -1e30f, mx1 = -1e30f;
#pragma unroll
        for (int nt = 0; nt < 8; nt++) {
            mx0 = fmaxf(mx0, fmaxf(s[nt][0], s[nt][1]));
            mx1 = fmaxf(mx1, fmaxf(s[nt][2], s[nt][3]));
        }
        mx0 = fmaxf(mx0, __shfl_xor_sync(0xffffffffu, mx0, 1));
        mx0 = fmaxf(mx0, __shfl_xor_sync(0xffffffffu, mx0, 2));
        mx1 = fmaxf(mx1, __shfl_xor_sync(0xffffffffu, mx1, 1));
        mx1 = fmaxf(mx1, __shfl_xor_sync(0xffffffffu, mx1, 2));

        const float mn0 = fmaxf(m0r, mx0);
        const float mn1 = fmaxf(m1r, mx1);
        const float sc0 = __expf(m0r - mn0);
        const float sc1 = __expf(m1r - mn1);
        m0r = mn0; m1r = mn1;

        float rs0 = 0.f, rs1 = 0.f;
#pragma unroll
        for (int nt = 0; nt < 8; nt++) {
            s[nt][0] = __expf(s[nt][0] - mn0); rs0 += s[nt][0];
            s[nt][1] = __expf(s[nt][1] - mn0); rs0 += s[nt][1];
            s[nt][2] = __expf(s[nt][2] - mn1); rs1 += s[nt][2];
            s[nt][3] = __expf(s[nt][3] - mn1); rs1 += s[nt][3];
        }
        rs0 += __shfl_xor_sync(0xffffffffu, rs0, 1);
        rs0 += __shfl_xor_sync(0xffffffffu, rs0, 2);
        rs1 += __shfl_xor_sync(0xffffffffu, rs1, 1);
        rs1 += __shfl_xor_sync(0xffffffffu, rs1, 2);
        l0r = l0r*sc0 + rs0;
        l1r = l1r*sc1 + rs1;

#pragma unroll
        for (int nt = 0; nt < 16; nt++) {
            o[nt][0] *= sc0; o[nt][1] *= sc0;
            o[nt][2] *= sc1; o[nt][3] *= sc1;
        }

        // ---- O += P V : P from S frags (FA2), split hi/lo ----
#pragma unroll
        for (int kc4 = 0; kc4 < 4; kc4++) {
            uint32_t aPh[4], aPl[4];
#pragma unroll
            for (int hh = 0; hh < 2; hh++) {
                const float pe0 = s[2*kc4+hh][0], po0 = s[2*kc4+hh][1];
                const float pe1 = s[2*kc4+hh][2], po1 = s[2*kc4+hh][3];
                const uint32_t ph0 = pack_bf16x2(pe0, po0);
                const uint32_t ph1 = pack_bf16x2(pe1, po1);
                aPh[2*hh]   = ph0;
                aPh[2*hh+1] = ph1;
                __nv_bfloat162 b0 = *(const __nv_bfloat162*)&ph0;
                __nv_bfloat162 b1 = *(const __nv_bfloat162*)&ph1;
                aPl[2*hh]   = pack_bf16x2(pe0 - __bfloat162float(b0.x),
                                          po0 - __bfloat162float(b0.y));
                aPl[2*hh+1] = pack_bf16x2(pe1 - __bfloat162float(b1.x),
                                          po1 - __bfloat162float(b1.y));
            }
#pragma unroll
            for (int nt = 0; nt < 16; nt++) {
                uint32_t vH[2], vL[2];
                const uint32_t vo = voff + (uint32_t)(kc4*(16*FSTR*2)) + nt*16;
                ldmat2t(vH, aVh + vo);
                ldmat2t(vL, aVl + vo);
                mma16816(o[nt], aPh, vH[0], vH[1]);
                mma16816(o[nt], aPh, vL[0], vL[1]);
                mma16816(o[nt], aPl, vH[0], vH[1]);
            }
        }
    }

    // ---- output ----
    const float li0 = 1.f / l0r, li1 = 1.f / l1r;
    const int rg = q0 + r0;
    const int cb = 2*(lane & 3);
#pragma unroll
    for (int nt = 0; nt < 16; nt++) {
        const int col = nt*8 + cb;
        *(float2*)&out[base + (size_t)rg*H_ + col] =
            make_float2(o[nt][0]*li0, o[nt][1]*li0);
        *(float2*)&out[base + (size_t)(rg+8)*H_ + col] =
            make_float2(o[nt][2]*li1, o[nt][3]*li1);
    }
}

// ---------------------------------------------------------------------------
extern "C" void kernel_launch(void* const* d_in, const int* in_sizes, int n_in,
                              void* d_out, int out_size)
{
    (void)in_sizes; (void)n_in; (void)out_size;
    const float* x  = (const float*)d_in[0];
    const float* Wq = (const float*)d_in[1];
    const float* Wk = (const float*)d_in[2];
    const float* Wv = (const float*)d_in[3];
    float* out = (float*)d_out;

    convert_w_kernel<<<dim3((D_*H_)/256, 3), 256>>>(Wq, Wk, Wv);

    proj_hmma_kernel<<<dim3(M_/128, 3), 256>>>(x);

    cudaFuncSetAttribute(flash3_kernel,
                         cudaFuncAttributeMaxDynamicSharedMemorySize, FSMEM);
    flash3_kernel<<<dim3(16, B_), 256, FSMEM>>>(out);
}

// round 11
// speedup vs baseline: 3.9154x; 1.1158x over previous
#include <cuda_runtime.h>
#include <cuda_bf16.h>
#include <math.h>
#include <stdint.h>

#define B_ 8
#define T_ 2048
#define D_ 2048
#define H_ 128
#define M_ (B_*T_)

// Scratch (alloc-free rules: __device__ globals)
__device__ __nv_bfloat16 g_qhi[M_*H_], g_qlo[M_*H_];   // q pre-scaled by sqrt(128)
__device__ __nv_bfloat16 g_khi[M_*H_], g_klo[M_*H_];
__device__ __nv_bfloat16 g_vhi[M_*H_], g_vlo[M_*H_];
__device__ __nv_bfloat16 g_wthi[3][H_*D_];             // W^T: [n][k], weight-major
__device__ __nv_bfloat16 g_wtlo[3][H_*D_];

// ---------------------------------------------------------------------------
// helpers
// ---------------------------------------------------------------------------
__device__ __forceinline__ uint32_t smem_u32(const void* p) {
    uint32_t a;
    asm("{ .reg .u64 t; cvta.to.shared.u64 t, %1; cvt.u32.u64 %0, t; }" : "=r"(a) : "l"(p));
    return a;
}
__device__ __forceinline__ void ldmat4(uint32_t* r, uint32_t addr) {
    asm volatile("ldmatrix.sync.aligned.m8n8.x4.shared.b16 {%0,%1,%2,%3}, [%4];"
        : "=r"(r[0]), "=r"(r[1]), "=r"(r[2]), "=r"(r[3]) : "r"(addr));
}
__device__ __forceinline__ void ldmat4t(uint32_t* r, uint32_t addr) {
    asm volatile("ldmatrix.sync.aligned.m8n8.x4.trans.shared.b16 {%0,%1,%2,%3}, [%4];"
        : "=r"(r[0]), "=r"(r[1]), "=r"(r[2]), "=r"(r[3]) : "r"(addr));
}
__device__ __forceinline__ void mma16816(float* d, const uint32_t* a,
                                         uint32_t b0, uint32_t b1) {
    asm volatile(
        "mma.sync.aligned.m16n8k16.row.col.f32.bf16.bf16.f32 "
        "{%0,%1,%2,%3}, {%4,%5,%6,%7}, {%8,%9}, {%0,%1,%2,%3};"
        : "+f"(d[0]), "+f"(d[1]), "+f"(d[2]), "+f"(d[3])
        : "r"(a[0]), "r"(a[1]), "r"(a[2]), "r"(a[3]), "r"(b0), "r"(b1));
}
__device__ __forceinline__ uint32_t pack_bf16x2(float even, float odd) {
    uint32_t r;
    asm("cvt.rn.bf16x2.f32 %0, %1, %2;" : "=r"(r) : "f"(odd), "f"(even));
    return r;
}
#define CP_ASYNC16(dst, src) \
    asm volatile("cp.async.cg.shared.global [%0], [%1], 16;" :: "r"(dst), "l"(src))
#define CP_COMMIT() asm volatile("cp.async.commit_group;" ::: "memory")
#define CP_WAIT1()  asm volatile("cp.async.wait_group 1;" ::: "memory")
#define CP_WAIT0()  asm volatile("cp.async.wait_group 0;" ::: "memory")

// ---------------------------------------------------------------------------
// W convert (unchanged)
// ---------------------------------------------------------------------------
__global__ __launch_bounds__(256) void convert_w_kernel(
    const float* __restrict__ Wq, const float* __restrict__ Wk, const float* __restrict__ Wv)
{
    const int w = blockIdx.y;
    const float* W = (w == 0) ? Wq : (w == 1) ? Wk : Wv;
    const int e = blockIdx.x * 256 + threadIdx.x;
    const int k = e >> 7, n = e & 127;
    float v = W[(size_t)k * H_ + n];
    __nv_bfloat16 h = __float2bfloat16(v);
    __nv_bfloat16 l = __float2bfloat16(v - __bfloat162float(h));
    g_wthi[w][(size_t)n * D_ + k] = h;
    g_wtlo[w][(size_t)n * D_ + k] = l;
}

// ---------------------------------------------------------------------------
// Projection v2: CTA = 128 rows x 384 cols (all 3 weights), grid 128.
// cp.async double-buffered (A raw fp32 + B bf16 hi/lo); x converted once.
// 8 warps = 2(M) x 4(N); warp tile 64x96. 3 split products: hh + hl + lh.
// ---------------------------------------------------------------------------
// smem byte offsets (16B aligned), dynamic:
#define PX_RAW(buf) ((buf)*18432u)                  // 2 x 128x36 fp32 (stride 144B)
#define PX_AHI      36864u                          // 128x40 bf16 (stride 80B)
#define PX_ALO      47104u
#define PX_BHI(buf) (57344u + (buf)*61440u)         // 384x40 bf16 hi (stride 80B)
#define PX_BLO(buf) (PX_BHI(buf) + 30720u)
#define PX_SMEM     180224

__global__ __launch_bounds__(256, 1) void proj_hmma2_kernel(const float* __restrict__ x)
{
    extern __shared__ char psm[];
    const uint32_t s0 = smem_u32(psm);

    const int t    = threadIdx.x;
    const int lane = t & 31;
    const int wid  = t >> 5;
    const int wm   = wid & 1;        // M half
    const int wn   = wid >> 1;       // N quarter (96 cols)
    const int m0   = blockIdx.x * 128;

    const __nv_bfloat16* WT_hi = &g_wthi[0][0];   // weight-major: row n in 0..383
    const __nv_bfloat16* WT_lo = &g_wtlo[0][0];

    float acc[4][12][4];
#pragma unroll
    for (int mt = 0; mt < 4; mt++)
#pragma unroll
        for (int nt = 0; nt < 12; nt++)
#pragma unroll
            for (int e = 0; e < 4; e++) acc[mt][nt][e] = 0.f;

    // cp.async index maps
    const int arow = t >> 1;                 // A: 2 thr/row, 4 x 16B each
    const int ac0  = (t & 1) * 4;            // 16B chunk index 0..7 (4 per thread)
    const int brow = t >> 2;                 // B: this + stride 64 rows, wait...
    // B: 1536 16B-chunks per component; thread does 6: idx = t + i*256
    // A issue helper below.

    // ldmatrix address components (relative to component bases)
    const uint32_t aoff = (uint32_t)(((wm*64 + (lane & 15))*40 + (lane >> 4)*8) * 2);
    const uint32_t boff = (uint32_t)(((wn*96 + (lane & 7) + ((lane >> 4) & 1)*8)*40
                                      + ((lane >> 3) & 1)*8) * 2);

    // ---- prologue: issue chunk 0 ----
    {
        const int buf = 0, k0 = 0;
#pragma unroll
        for (int i = 0; i < 4; i++) {
            const int c = ac0 + i;
            CP_ASYNC16(s0 + PX_RAW(buf) + (uint32_t)(arow*144 + c*16),
                       x + (size_t)(m0 + arow) * D_ + k0 + c*4);
        }
#pragma unroll
        for (int i = 0; i < 6; i++) {
            const int idx = t + i*256;
            const int n = idx >> 2, c = idx & 3;
            CP_ASYNC16(s0 + PX_BHI(buf) + (uint32_t)(n*80 + c*16),
                       WT_hi + (size_t)n * D_ + k0 + c*8);
            CP_ASYNC16(s0 + PX_BLO(buf) + (uint32_t)(n*80 + c*16),
                       WT_lo + (size_t)n * D_ + k0 + c*8);
        }
        CP_COMMIT();
    }

    for (int ch = 0; ch < 64; ch++) {
        const int buf = ch & 1;
        __syncthreads();                        // compute(ch-1) done with its buffers

        if (ch < 63) {                          // issue ch+1
            const int nbuf = buf ^ 1;
            const int k0 = (ch + 1) * 32;
#pragma unroll
            for (int i = 0; i < 4; i++) {
                const int c = ac0 + i;
                CP_ASYNC16(s0 + PX_RAW(nbuf) + (uint32_t)(arow*144 + c*16),
                           x + (size_t)(m0 + arow) * D_ + k0 + c*4);
            }
#pragma unroll
            for (int i = 0; i < 6; i++) {
                const int idx = t + i*256;
                const int n = idx >> 2, c = idx & 3;
                CP_ASYNC16(s0 + PX_BHI(nbuf) + (uint32_t)(n*80 + c*16),
                           WT_hi + (size_t)n * D_ + k0 + c*8);
                CP_ASYNC16(s0 + PX_BLO(nbuf) + (uint32_t)(n*80 + c*16),
                           WT_lo + (size_t)n * D_ + k0 + c*8);
            }
            CP_COMMIT();
            CP_WAIT1();                         // chunk ch landed; ch+1 in flight
        } else {
            CP_WAIT0();
        }
        __syncthreads();

        // ---- convert A raw fp32 -> bf16 hi/lo (once for all 3 weights) ----
        {
            const int row = t >> 1, half = t & 1;
            const char* rsrc = psm + PX_RAW(buf) + row*144 + half*64;
            char* dhi = psm + PX_AHI + (row*40 + half*16)*2;
            char* dlo = psm + PX_ALO + (row*40 + half*16)*2;
#pragma unroll
            for (int j = 0; j < 4; j++) {
                float4 v = *(const float4*)(rsrc + j*16);
                uint32_t h01 = pack_bf16x2(v.x, v.y);
                uint32_t h23 = pack_bf16x2(v.z, v.w);
                __nv_bfloat162 b01 = *(const __nv_bfloat162*)&h01;
                __nv_bfloat162 b23 = *(const __nv_bfloat162*)&h23;
                uint32_t l01 = pack_bf16x2(v.x - __bfloat162float(b01.x),
                                           v.y - __bfloat162float(b01.y));
                uint32_t l23 = pack_bf16x2(v.z - __bfloat162float(b23.x),
                                           v.w - __bfloat162float(b23.y));
                *(uint32_t*)(dhi + j*8)     = h01;
                *(uint32_t*)(dhi + j*8 + 4) = h23;
                *(uint32_t*)(dlo + j*8)     = l01;
                *(uint32_t*)(dlo + j*8 + 4) = l23;
            }
        }
        __syncthreads();

        // ---- compute ----
        const uint32_t bbase_h = s0 + PX_BHI(buf) + boff;
        const uint32_t bbase_l = s0 + PX_BLO(buf) + boff;
#pragma unroll
        for (int ks = 0; ks < 2; ks++) {
            uint32_t a[4][4];
            // pass 1: A = hi -> hh + hl
#pragma unroll
            for (int mt = 0; mt < 4; mt++)
                ldmat4(a[mt], s0 + PX_AHI + aoff + (uint32_t)(mt*1280 + ks*32));
#pragma unroll
            for (int np = 0; np < 6; np++) {
                uint32_t bh[4], bl[4];
                ldmat4(bh, bbase_h + (uint32_t)(np*1280 + ks*32));
                ldmat4(bl, bbase_l + (uint32_t)(np*1280 + ks*32));
#pragma unroll
                for (int mt = 0; mt < 4; mt++) {
                    mma16816(acc[mt][2*np],   a[mt], bh[0], bh[1]);
                    mma16816(acc[mt][2*np+1], a[mt], bh[2], bh[3]);
                }
#pragma unroll
                for (int mt = 0; mt < 4; mt++) {
                    mma16816(acc[mt][2*np],   a[mt], bl[0], bl[1]);
                    mma16816(acc[mt][2*np+1], a[mt], bl[2], bl[3]);
                }
            }
            // pass 2: A = lo -> lh
#pragma unroll
            for (int mt = 0; mt < 4; mt++)
                ldmat4(a[mt], s0 + PX_ALO + aoff + (uint32_t)(mt*1280 + ks*32));
#pragma unroll
            for (int np = 0; np < 6; np++) {
                uint32_t bh[4];
                ldmat4(bh, bbase_h + (uint32_t)(np*1280 + ks*32));
#pragma unroll
                for (int mt = 0; mt < 4; mt++) {
                    mma16816(acc[mt][2*np],   a[mt], bh[0], bh[1]);
                    mma16816(acc[mt][2*np+1], a[mt], bh[2], bh[3]);
                }
            }
        }
    }

    // ---- epilogue: split to bf16 hi/lo, q scaled by sqrt(128) ----
    const int dr = lane >> 2;
    const int dc = (lane & 3) * 2;
#pragma unroll
    for (int mt = 0; mt < 4; mt++) {
#pragma unroll
        for (int nt = 0; nt < 12; nt++) {
            const int cg  = wn*96 + nt*8 + dc;      // global col 0..383
            const int w   = cg >> 7;
            const int col = cg & 127;
            __nv_bfloat16* ohi = (w == 0) ? g_qhi : (w == 1) ? g_khi : g_vhi;
            __nv_bfloat16* olo = (w == 0) ? g_qlo : (w == 1) ? g_klo : g_vlo;
            const float sc = (w == 0) ? 11.313708498984761f : 1.0f;
            const int row = m0 + wm*64 + mt*16 + dr;
#pragma unroll
            for (int half = 0; half < 2; half++) {
                const int rr = row + half*8;
                float v0 = acc[mt][nt][half*2 + 0] * sc;
                float v1 = acc[mt][nt][half*2 + 1] * sc;
                uint32_t h = pack_bf16x2(v0, v1);
                __nv_bfloat162 bh = *(const __nv_bfloat162*)&h;
                uint32_t l = pack_bf16x2(v0 - __bfloat162float(bh.x),
                                         v1 - __bfloat162float(bh.y));
                *(uint32_t*)(ohi + (size_t)rr * H_ + col) = h;
                *(uint32_t*)(olo + (size_t)rr * H_ + col) = l;
            }
        }
    }
}

// ---------------------------------------------------------------------------
// Flash attention v3.1 — HMMA FA2; S drops the ll product; PV uses x4.trans.
// CTA = 2 independent 128-thread groups (named barriers), each BM=64 q rows.
// ---------------------------------------------------------------------------
#define FSTR 136
#define FQH  (64*FSTR)
#define FGRP (6*FQH)
#define FSMEM (2*FGRP*2)

__global__ __launch_bounds__(256) void flash3_kernel(float* __restrict__ out)
{
    extern __shared__ __nv_bfloat16 fsm[];
    const int t    = threadIdx.x;
    const int g    = t >> 7;
    const int gt   = t & 127;
    const int warp = gt >> 5;
    const int lane = t & 31;
    const int b    = blockIdx.y;
    const int p    = blockIdx.x;
    const int qb   = g ? p : (31 - p);
    const int q0   = qb * 64;
    const size_t base = (size_t)b * T_ * H_;

    __nv_bfloat16* sQh = fsm + g*FGRP;
    __nv_bfloat16* sQl = sQh + FQH;
    __nv_bfloat16* sKh = sQl + FQH;
    __nv_bfloat16* sKl = sKh + FQH;
    __nv_bfloat16* sVh = sKl + FQH;
    __nv_bfloat16* sVl = sVh + FQH;
    const uint32_t aQh = smem_u32(sQh), aQl = smem_u32(sQl);
    const uint32_t aKh = smem_u32(sKh), aKl = smem_u32(sKl);
    const uint32_t aVh = smem_u32(sVh), aVl = smem_u32(sVl);

#pragma unroll
    for (int i = 0; i < 8; i++) {
        const int idx = gt + i*128;
        const int row = idx >> 4, c = idx & 15;
        const size_t go = base + (size_t)(q0 + row)*H_ + c*8;
        *(uint4*)(sQh + row*FSTR + c*8) = *(const uint4*)(g_qhi + go);
        *(uint4*)(sQl + row*FSTR + c*8) = *(const uint4*)(g_qlo + go);
    }

    float o[16][4];
#pragma unroll
    for (int nt = 0; nt < 16; nt++)
#pragma unroll
        for (int e = 0; e < 4; e++) o[nt][e] = 0.f;
    float m0r = -1e30f, m1r = -1e30f, l0r = 0.f, l1r = 0.f;

    const uint32_t aoff = (uint32_t)(((warp*16 + (lane & 15))*FSTR + (lane >> 4)*8) * 2);
    const uint32_t boff = (uint32_t)((((lane & 7) + ((lane >> 4) & 1)*8)*FSTR
                                      + ((lane >> 3) & 1)*8) * 2);
    const uint32_t voff4 = (uint32_t)(((lane & 15)*FSTR)*2 + (lane >> 4)*16);

    const int r0 = warp*16 + (lane >> 2);

    for (int kb = 0; kb <= qb; kb++) {
        const int k0 = kb * 64;
        asm volatile("bar.sync %0, %1;" :: "r"(g+1), "r"(128) : "memory");

#pragma unroll
        for (int i = 0; i < 8; i++) {
            const int idx = gt + i*128;
            const int row = idx >> 4, c = idx & 15;
            const size_t go = base + (size_t)(k0 + row)*H_ + c*8;
            *(uint4*)(sKh + row*FSTR + c*8) = *(const uint4*)(g_khi + go);
            *(uint4*)(sKl + row*FSTR + c*8) = *(const uint4*)(g_klo + go);
            *(uint4*)(sVh + row*FSTR + c*8) = *(const uint4*)(g_vhi + go);
            *(uint4*)(sVl + row*FSTR + c*8) = *(const uint4*)(g_vlo + go);
        }
        asm volatile("bar.sync %0, %1;" :: "r"(g+1), "r"(128) : "memory");

        // ---- S = Q K^T : hh + hl + lh (ll negligible) ----
        float s[8][4];
#pragma unroll
        for (int nt = 0; nt < 8; nt++)
#pragma unroll
            for (int e = 0; e < 4; e++) s[nt][e] = 0.f;

#pragma unroll
        for (int kc = 0; kc < 8; kc++) {
            uint32_t aH[4], aL[4];
            ldmat4(aH, aQh + aoff + kc*32);
            ldmat4(aL, aQl + aoff + kc*32);
#pragma unroll
            for (int ntp = 0; ntp < 4; ntp++) {
                uint32_t bH[4], bL[4];
                const uint32_t bo = boff + (uint32_t)(ntp*(16*FSTR*2)) + kc*32;
                ldmat4(bH, aKh + bo);
                ldmat4(bL, aKl + bo);
#pragma unroll
                for (int h = 0; h < 2; h++) {
                    const int nt = ntp*2 + h;
                    mma16816(s[nt], aH, bH[2*h], bH[2*h+1]);
                    mma16816(s[nt], aH, bL[2*h], bL[2*h+1]);
                    mma16816(s[nt], aL, bH[2*h], bH[2*h+1]);
                }
            }
        }

        if (kb == qb) {
#pragma unroll
            for (int nt = 0; nt < 8; nt++) {
                const int c0 = nt*8 + 2*(lane & 3);
                if (c0     > r0)     s[nt][0] = -1e9f;
                if (c0 + 1 > r0)     s[nt][1] = -1e9f;
                if (c0     > r0 + 8) s[nt][2] = -1e9f;
                if (c0 + 1 > r0 + 8) s[nt][3] = -1e9f;
            }
        }

        float mx0 = -1e30f, mx1 = -1e30f;
#pragma unroll
        for (int nt = 0; nt < 8; nt++) {
            mx0 = fmaxf(mx0, fmaxf(s[nt][0], s[nt][1]));
            mx1 = fmaxf(mx1, fmaxf(s[nt][2], s[nt][3]));
        }
        mx0 = fmaxf(mx0, __shfl_xor_sync(0xffffffffu, mx0, 1));
        mx0 = fmaxf(mx0, __shfl_xor_sync(0xffffffffu, mx0, 2));
        mx1 = fmaxf(mx1, __shfl_xor_sync(0xffffffffu, mx1, 1));
        mx1 = fmaxf(mx1, __shfl_xor_sync(0xffffffffu, mx1, 2));

        const float mn0 = fmaxf(m0r, mx0);
        const float mn1 = fmaxf(m1r, mx1);
        const float sc0 = __expf(m0r - mn0);
        const float sc1 = __expf(m1r - mn1);
        m0r = mn0; m1r = mn1;

        float rs0 = 0.f, rs1 = 0.f;
#pragma unroll
        for (int nt = 0; nt < 8; nt++) {
            s[nt][0] = __expf(s[nt][0] - mn0); rs0 += s[nt][0];
            s[nt][1] = __expf(s[nt][1] - mn0); rs0 += s[nt][1];
            s[nt][2] = __expf(s[nt][2] - mn1); rs1 += s[nt][2];
            s[nt][3] = __expf(s[nt][3] - mn1); rs1 += s[nt][3];
        }
        rs0 += __shfl_xor_sync(0xffffffffu, rs0, 1);
        rs0 += __shfl_xor_sync(0xffffffffu, rs0, 2);
        rs1 += __shfl_xor_sync(0xffffffffu, rs1, 1);
        rs1 += __shfl_xor_sync(0xffffffffu, rs1, 2);
        l0r = l0r*sc0 + rs0;
        l1r = l1r*sc1 + rs1;

#pragma unroll
        for (int nt = 0; nt < 16; nt++) {
            o[nt][0] *= sc0; o[nt][1] *= sc0;
            o[nt][2] *= sc1; o[nt][3] *= sc1;
        }

        // ---- O += P V (x4.trans V loads; Ph*Vh + Ph*Vl + Pl*Vh) ----
#pragma unroll
        for (int kc4 = 0; kc4 < 4; kc4++) {
            uint32_t aPh[4], aPl[4];
#pragma unroll
            for (int hh = 0; hh < 2; hh++) {
                const float pe0 = s[2*kc4+hh][0], po0 = s[2*kc4+hh][1];
                const float pe1 = s[2*kc4+hh][2], po1 = s[2*kc4+hh][3];
                const uint32_t ph0 = pack_bf16x2(pe0, po0);
                const uint32_t ph1 = pack_bf16x2(pe1, po1);
                aPh[2*hh]   = ph0;
                aPh[2*hh+1] = ph1;
                __nv_bfloat162 b0 = *(const __nv_bfloat162*)&ph0;
                __nv_bfloat162 b1 = *(const __nv_bfloat162*)&ph1;
                aPl[2*hh]   = pack_bf16x2(pe0 - __bfloat162float(b0.x),
                                          po0 - __bfloat162float(b0.y));
                aPl[2*hh+1] = pack_bf16x2(pe1 - __bfloat162float(b1.x),
                                          po1 - __bfloat162float(b1.y));
            }
#pragma unroll
            for (int ntp = 0; ntp < 8; ntp++) {
                uint32_t vH[4], vL[4];
                const uint32_t vo = voff4 + (uint32_t)(kc4*(16*FSTR*2)) + ntp*32;
                ldmat4t(vH, aVh + vo);
                ldmat4t(vL, aVl + vo);
                mma16816(o[2*ntp],   aPh, vH[0], vH[1]);
                mma16816(o[2*ntp+1], aPh, vH[2], vH[3]);
                mma16816(o[2*ntp],   aPh, vL[0], vL[1]);
                mma16816(o[2*ntp+1], aPh, vL[2], vL[3]);
                mma16816(o[2*ntp],   aPl, vH[0], vH[1]);
                mma16816(o[2*ntp+1], aPl, vH[2], vH[3]);
            }
        }
    }

    const float li0 = 1.f / l0r, li1 = 1.f / l1r;
    const int rg = q0 + r0;
    const int cb = 2*(lane & 3);
#pragma unroll
    for (int nt = 0; nt < 16; nt++) {
        const int col = nt*8 + cb;
        *(float2*)&out[base + (size_t)rg*H_ + col] =
            make_float2(o[nt][0]*li0, o[nt][1]*li0);
        *(float2*)&out[base + (size_t)(rg+8)*H_ + col] =
            make_float2(o[nt][2]*li1, o[nt][3]*li1);
    }
}

// ---------------------------------------------------------------------------
extern "C" void kernel_launch(void* const* d_in, const int* in_sizes, int n_in,
                              void* d_out, int out_size)
{
    (void)in_sizes; (void)n_in; (void)out_size;
    const float* x  = (const float*)d_in[0];
    const float* Wq = (const float*)d_in[1];
    const float* Wk = (const float*)d_in[2];
    const float* Wv = (const float*)d_in[3];
    float* out = (float*)d_out;

    convert_w_kernel<<<dim3((D_*H_)/256, 3), 256>>>(Wq, Wk, Wv);

    cudaFuncSetAttribute(proj_hmma2_kernel,
                         cudaFuncAttributeMaxDynamicSharedMemorySize, PX_SMEM);
    proj_hmma2_kernel<<<M_/128, 256, PX_SMEM>>>(x);

    cudaFuncSetAttribute(flash3_kernel,
                         cudaFuncAttributeMaxDynamicSharedMemorySize, FSMEM);
    flash3_kernel<<<dim3(16, B_), 256, FSMEM>>>(out);
}

// round 12
// speedup vs baseline: 3.9340x; 1.0047x over previous
#include <cuda_runtime.h>
#include <cuda_bf16.h>
#include <math.h>
#include <stdint.h>

#define B_ 8
#define T_ 2048
#define D_ 2048
#define H_ 128
#define M_ (B_*T_)

// Scratch (alloc-free rules: __device__ globals)
__device__ __nv_bfloat16 g_qhi[M_*H_], g_qlo[M_*H_];   // q pre-scaled by sqrt(128)
__device__ __nv_bfloat16 g_khi[M_*H_], g_klo[M_*H_];
__device__ __nv_bfloat16 g_vhi[M_*H_], g_vlo[M_*H_];
__device__ __nv_bfloat16 g_wthi[3][H_*D_];             // W^T: [n][k], weight-major
__device__ __nv_bfloat16 g_wtlo[3][H_*D_];

// ---------------------------------------------------------------------------
// helpers
// ---------------------------------------------------------------------------
__device__ __forceinline__ uint32_t smem_u32(const void* p) {
    uint32_t a;
    asm("{ .reg .u64 t; cvta.to.shared.u64 t, %1; cvt.u32.u64 %0, t; }" : "=r"(a) : "l"(p));
    return a;
}
__device__ __forceinline__ void ldmat4(uint32_t* r, uint32_t addr) {
    asm volatile("ldmatrix.sync.aligned.m8n8.x4.shared.b16 {%0,%1,%2,%3}, [%4];"
        : "=r"(r[0]), "=r"(r[1]), "=r"(r[2]), "=r"(r[3]) : "r"(addr));
}
__device__ __forceinline__ void ldmat4t(uint32_t* r, uint32_t addr) {
    asm volatile("ldmatrix.sync.aligned.m8n8.x4.trans.shared.b16 {%0,%1,%2,%3}, [%4];"
        : "=r"(r[0]), "=r"(r[1]), "=r"(r[2]), "=r"(r[3]) : "r"(addr));
}
__device__ __forceinline__ void mma16816(float* d, const uint32_t* a,
                                         uint32_t b0, uint32_t b1) {
    asm volatile(
        "mma.sync.aligned.m16n8k16.row.col.f32.bf16.bf16.f32 "
        "{%0,%1,%2,%3}, {%4,%5,%6,%7}, {%8,%9}, {%0,%1,%2,%3};"
        : "+f"(d[0]), "+f"(d[1]), "+f"(d[2]), "+f"(d[3])
        : "r"(a[0]), "r"(a[1]), "r"(a[2]), "r"(a[3]), "r"(b0), "r"(b1));
}
__device__ __forceinline__ uint32_t pack_bf16x2(float even, float odd) {
    uint32_t r;
    asm("cvt.rn.bf16x2.f32 %0, %1, %2;" : "=r"(r) : "f"(odd), "f"(even));
    return r;
}
#define CP_ASYNC16(dst, src) \
    asm volatile("cp.async.cg.shared.global [%0], [%1], 16;" :: "r"(dst), "l"(src))
#define CP_COMMIT() asm volatile("cp.async.commit_group;" ::: "memory")
#define CP_WAIT0()  asm volatile("cp.async.wait_group 0;" ::: "memory")

// ---------------------------------------------------------------------------
// W convert (unchanged)
// ---------------------------------------------------------------------------
__global__ __launch_bounds__(256) void convert_w_kernel(
    const float* __restrict__ Wq, const float* __restrict__ Wk, const float* __restrict__ Wv)
{
    const int w = blockIdx.y;
    const float* W = (w == 0) ? Wq : (w == 1) ? Wk : Wv;
    const int e = blockIdx.x * 256 + threadIdx.x;
    const int k = e >> 7, n = e & 127;
    float v = W[(size_t)k * H_ + n];
    __nv_bfloat16 h = __float2bfloat16(v);
    __nv_bfloat16 l = __float2bfloat16(v - __bfloat162float(h));
    g_wthi[w][(size_t)n * D_ + k] = h;
    g_wtlo[w][(size_t)n * D_ + k] = l;
}

// ---------------------------------------------------------------------------
// Projection v3: CTA = 128 rows x 384 cols (all 3 weights), grid 128.
// 2-barrier pipeline:  wait0 -> sync -> convert(A) -> sync -> {issue ch+1 + compute}
// All buffers double-buffered; cp.async issue interleaved with MMA.
// ---------------------------------------------------------------------------
// smem byte offsets:
#define PX_RAW(buf) ((buf)*18432u)                  // 128 x 144B fp32 raw A
#define PX_AHI(buf) (36864u + (buf)*20480u)         // 128x40 bf16 hi (stride 80B)
#define PX_ALO(buf) (PX_AHI(buf) + 10240u)
#define PX_BHI(buf) (77824u + (buf)*61440u)         // 384x40 bf16 hi (stride 80B)
#define PX_BLO(buf) (PX_BHI(buf) + 30720u)
#define PX_SMEM     200704

__global__ __launch_bounds__(256, 1) void proj_hmma3_kernel(const float* __restrict__ x)
{
    extern __shared__ char psm[];
    const uint32_t s0 = smem_u32(psm);

    const int t    = threadIdx.x;
    const int lane = t & 31;
    const int wid  = t >> 5;
    const int wm   = wid & 1;        // M half
    const int wn   = wid >> 1;       // N quarter (96 cols)
    const int m0   = blockIdx.x * 128;

    const __nv_bfloat16* WT_hi = &g_wthi[0][0];   // weight-major: row n in 0..383
    const __nv_bfloat16* WT_lo = &g_wtlo[0][0];

    float acc[4][12][4];
#pragma unroll
    for (int mt = 0; mt < 4; mt++)
#pragma unroll
        for (int nt = 0; nt < 12; nt++)
#pragma unroll
            for (int e = 0; e < 4; e++) acc[mt][nt][e] = 0.f;

    // cp.async index maps
    const int arow = t >> 1;                 // A: 2 thr/row, 4 x 16B each
    const int ac0  = (t & 1) * 4;

    // ldmatrix address components (relative to component bases)
    const uint32_t aoff = (uint32_t)(((wm*64 + (lane & 15))*40 + (lane >> 4)*8) * 2);
    const uint32_t boff = (uint32_t)(((wn*96 + (lane & 7) + ((lane >> 4) & 1)*8)*40
                                      + ((lane >> 3) & 1)*8) * 2);

    // ---- prologue: issue chunk 0 ----
    {
#pragma unroll
        for (int i = 0; i < 4; i++) {
            const int c = ac0 + i;
            CP_ASYNC16(s0 + PX_RAW(0) + (uint32_t)(arow*144 + c*16),
                       x + (size_t)(m0 + arow) * D_ + c*4);
        }
#pragma unroll
        for (int i = 0; i < 6; i++) {
            const int idx = t + i*256;
            const int n = idx >> 2, c = idx & 3;
            CP_ASYNC16(s0 + PX_BHI(0) + (uint32_t)(n*80 + c*16),
                       WT_hi + (size_t)n * D_ + c*8);
            CP_ASYNC16(s0 + PX_BLO(0) + (uint32_t)(n*80 + c*16),
                       WT_lo + (size_t)n * D_ + c*8);
        }
        CP_COMMIT();
    }

    for (int ch = 0; ch < 64; ch++) {
        const int buf = ch & 1;

        CP_WAIT0();                 // only group ch is in flight here
        __syncthreads();            // + all warps done with compute(ch-1)

        // ---- convert A raw fp32 -> bf16 hi/lo (short region) ----
        {
            const int row = t >> 1, half = t & 1;
            const char* rsrc = psm + PX_RAW(buf) + row*144 + half*64;
            char* dhi = psm + PX_AHI(buf) + (row*40 + half*16)*2;
            char* dlo = psm + PX_ALO(buf) + (row*40 + half*16)*2;
#pragma unroll
            for (int j = 0; j < 4; j++) {
                float4 v = *(const float4*)(rsrc + j*16);
                uint32_t h01 = pack_bf16x2(v.x, v.y);
                uint32_t h23 = pack_bf16x2(v.z, v.w);
                __nv_bfloat162 b01 = *(const __nv_bfloat162*)&h01;
                __nv_bfloat162 b23 = *(const __nv_bfloat162*)&h23;
                uint32_t l01 = pack_bf16x2(v.x - __bfloat162float(b01.x),
                                           v.y - __bfloat162float(b01.y));
                uint32_t l23 = pack_bf16x2(v.z - __bfloat162float(b23.x),
                                           v.w - __bfloat162float(b23.y));
                *(uint32_t*)(dhi + j*8)     = h01;
                *(uint32_t*)(dhi + j*8 + 4) = h23;
                *(uint32_t*)(dlo + j*8)     = l01;
                *(uint32_t*)(dlo + j*8 + 4) = l23;
            }
        }
        __syncthreads();

        // ---- issue chunk ch+1 (interleaves with MMA below) ----
        if (ch < 63) {
            const int nbuf = buf ^ 1;
            const int k0 = (ch + 1) * 32;
#pragma unroll
            for (int i = 0; i < 4; i++) {
                const int c = ac0 + i;
                CP_ASYNC16(s0 + PX_RAW(nbuf) + (uint32_t)(arow*144 + c*16),
                           x + (size_t)(m0 + arow) * D_ + k0 + c*4);
            }
#pragma unroll
            for (int i = 0; i < 6; i++) {
                const int idx = t + i*256;
                const int n = idx >> 2, c = idx & 3;
                CP_ASYNC16(s0 + PX_BHI(nbuf) + (uint32_t)(n*80 + c*16),
                           WT_hi + (size_t)n * D_ + k0 + c*8);
                CP_ASYNC16(s0 + PX_BLO(nbuf) + (uint32_t)(n*80 + c*16),
                           WT_lo + (size_t)n * D_ + k0 + c*8);
            }
            CP_COMMIT();
        }

        // ---- compute chunk ch ----
        const uint32_t abase_h = s0 + PX_AHI(buf) + aoff;
        const uint32_t abase_l = s0 + PX_ALO(buf) + aoff;
        const uint32_t bbase_h = s0 + PX_BHI(buf) + boff;
        const uint32_t bbase_l = s0 + PX_BLO(buf) + boff;
#pragma unroll
        for (int ks = 0; ks < 2; ks++) {
            uint32_t a[4][4];
            // pass 1: A = hi -> hh + hl
#pragma unroll
            for (int mt = 0; mt < 4; mt++)
                ldmat4(a[mt], abase_h + (uint32_t)(mt*1280 + ks*32));
#pragma unroll
            for (int np = 0; np < 6; np++) {
                uint32_t bh[4], bl[4];
                ldmat4(bh, bbase_h + (uint32_t)(np*1280 + ks*32));
                ldmat4(bl, bbase_l + (uint32_t)(np*1280 + ks*32));
#pragma unroll
                for (int mt = 0; mt < 4; mt++) {
                    mma16816(acc[mt][2*np],   a[mt], bh[0], bh[1]);
                    mma16816(acc[mt][2*np+1], a[mt], bh[2], bh[3]);
                }
#pragma unroll
                for (int mt = 0; mt < 4; mt++) {
                    mma16816(acc[mt][2*np],   a[mt], bl[0], bl[1]);
                    mma16816(acc[mt][2*np+1], a[mt], bl[2], bl[3]);
                }
            }
            // pass 2: A = lo -> lh
#pragma unroll
            for (int mt = 0; mt < 4; mt++)
                ldmat4(a[mt], abase_l + (uint32_t)(mt*1280 + ks*32));
#pragma unroll
            for (int np = 0; np < 6; np++) {
                uint32_t bh[4];
                ldmat4(bh, bbase_h + (uint32_t)(np*1280 + ks*32));
#pragma unroll
                for (int mt = 0; mt < 4; mt++) {
                    mma16816(acc[mt][2*np],   a[mt], bh[0], bh[1]);
                    mma16816(acc[mt][2*np+1], a[mt], bh[2], bh[3]);
                }
            }
        }
    }

    // ---- epilogue: split to bf16 hi/lo, q scaled by sqrt(128) ----
    const int dr = lane >> 2;
    const int dc = (lane & 3) * 2;
#pragma unroll
    for (int mt = 0; mt < 4; mt++) {
#pragma unroll
        for (int nt = 0; nt < 12; nt++) {
            const int cg  = wn*96 + nt*8 + dc;      // global col 0..383
            const int w   = cg >> 7;
            const int col = cg & 127;
            __nv_bfloat16* ohi = (w == 0) ? g_qhi : (w == 1) ? g_khi : g_vhi;
            __nv_bfloat16* olo = (w == 0) ? g_qlo : (w == 1) ? g_klo : g_vlo;
            const float sc = (w == 0) ? 11.313708498984761f : 1.0f;
            const int row = m0 + wm*64 + mt*16 + dr;
#pragma unroll
            for (int half = 0; half < 2; half++) {
                const int rr = row + half*8;
                float v0 = acc[mt][nt][half*2 + 0] * sc;
                float v1 = acc[mt][nt][half*2 + 1] * sc;
                uint32_t h = pack_bf16x2(v0, v1);
                __nv_bfloat162 bh = *(const __nv_bfloat162*)&h;
                uint32_t l = pack_bf16x2(v0 - __bfloat162float(bh.x),
                                         v1 - __bfloat162float(bh.y));
                *(uint32_t*)(ohi + (size_t)rr * H_ + col) = h;
                *(uint32_t*)(olo + (size_t)rr * H_ + col) = l;
            }
        }
    }
}

// ---------------------------------------------------------------------------
// Flash attention v3.1 (unchanged — at HMMA issue floor)
// ---------------------------------------------------------------------------
#define FSTR 136
#define FQH  (64*FSTR)
#define FGRP (6*FQH)
#define FSMEM (2*FGRP*2)

__global__ __launch_bounds__(256) void flash3_kernel(float* __restrict__ out)
{
    extern __shared__ __nv_bfloat16 fsm[];
    const int t    = threadIdx.x;
    const int g    = t >> 7;
    const int gt   = t & 127;
    const int warp = gt >> 5;
    const int lane = t & 31;
    const int b    = blockIdx.y;
    const int p    = blockIdx.x;
    const int qb   = g ? p : (31 - p);
    const int q0   = qb * 64;
    const size_t base = (size_t)b * T_ * H_;

    __nv_bfloat16* sQh = fsm + g*FGRP;
    __nv_bfloat16* sQl = sQh + FQH;
    __nv_bfloat16* sKh = sQl + FQH;
    __nv_bfloat16* sKl = sKh + FQH;
    __nv_bfloat16* sVh = sKl + FQH;
    __nv_bfloat16* sVl = sVh + FQH;
    const uint32_t aQh = smem_u32(sQh), aQl = smem_u32(sQl);
    const uint32_t aKh = smem_u32(sKh), aKl = smem_u32(sKl);
    const uint32_t aVh = smem_u32(sVh), aVl = smem_u32(sVl);

#pragma unroll
    for (int i = 0; i < 8; i++) {
        const int idx = gt + i*128;
        const int row = idx >> 4, c = idx & 15;
        const size_t go = base + (size_t)(q0 + row)*H_ + c*8;
        *(uint4*)(sQh + row*FSTR + c*8) = *(const uint4*)(g_qhi + go);
        *(uint4*)(sQl + row*FSTR + c*8) = *(const uint4*)(g_qlo + go);
    }

    float o[16][4];
#pragma unroll
    for (int nt = 0; nt < 16; nt++)
#pragma unroll
        for (int e = 0; e < 4; e++) o[nt][e] = 0.f;
    float m0r = -1e30f, m1r = -1e30f, l0r = 0.f, l1r = 0.f;

    const uint32_t aoff = (uint32_t)(((warp*16 + (lane & 15))*FSTR + (lane >> 4)*8) * 2);
    const uint32_t boff = (uint32_t)((((lane & 7) + ((lane >> 4) & 1)*8)*FSTR
                                      + ((lane >> 3) & 1)*8) * 2);
    const uint32_t voff4 = (uint32_t)(((lane & 15)*FSTR)*2 + (lane >> 4)*16);

    const int r0 = warp*16 + (lane >> 2);

    for (int kb = 0; kb <= qb; kb++) {
        const int k0 = kb * 64;
        asm volatile("bar.sync %0, %1;" :: "r"(g+1), "r"(128) : "memory");

#pragma unroll
        for (int i = 0; i < 8; i++) {
            const int idx = gt + i*128;
            const int row = idx >> 4, c = idx & 15;
            const size_t go = base + (size_t)(k0 + row)*H_ + c*8;
            *(uint4*)(sKh + row*FSTR + c*8) = *(const uint4*)(g_khi + go);
            *(uint4*)(sKl + row*FSTR + c*8) = *(const uint4*)(g_klo + go);
            *(uint4*)(sVh + row*FSTR + c*8) = *(const uint4*)(g_vhi + go);
            *(uint4*)(sVl + row*FSTR + c*8) = *(const uint4*)(g_vlo + go);
        }
        asm volatile("bar.sync %0, %1;" :: "r"(g+1), "r"(128) : "memory");

        // ---- S = Q K^T : hh + hl + lh ----
        float s[8][4];
#pragma unroll
        for (int nt = 0; nt < 8; nt++)
#pragma unroll
            for (int e = 0; e < 4; e++) s[nt][e] = 0.f;

#pragma unroll
        for (int kc = 0; kc < 8; kc++) {
            uint32_t aH[4], aL[4];
            ldmat4(aH, aQh + aoff + kc*32);
            ldmat4(aL, aQl + aoff + kc*32);
#pragma unroll
            for (int ntp = 0; ntp < 4; ntp++) {
                uint32_t bH[4], bL[4];
                const uint32_t bo = boff + (uint32_t)(ntp*(16*FSTR*2)) + kc*32;
                ldmat4(bH, aKh + bo);
                ldmat4(bL, aKl + bo);
#pragma unroll
                for (int h = 0; h < 2; h++) {
                    const int nt = ntp*2 + h;
                    mma16816(s[nt], aH, bH[2*h], bH[2*h+1]);
                    mma16816(s[nt], aH, bL[2*h], bL[2*h+1]);
                    mma16816(s[nt], aL, bH[2*h], bH[2*h+1]);
                }
            }
        }

        if (kb == qb) {
#pragma unroll
            for (int nt = 0; nt < 8; nt++) {
                const int c0 = nt*8 + 2*(lane & 3);
                if (c0     > r0)     s[nt][0] = -1e9f;
                if (c0 + 1 > r0)     s[nt][1] = -1e9f;
                if (c0     > r0 + 8) s[nt][2] = -1e9f;
                if (c0 + 1 > r0 + 8) s[nt][3] = -1e9f;
            }
        }

        float mx0 = -1e30f, mx1 = -1e30f;
#pragma unroll
        for (int nt = 0; nt < 8; nt++) {
            mx0 = fmaxf(mx0, fmaxf(s[nt][0], s[nt][1]));
            mx1 = fmaxf(mx1, fmaxf(s[nt][2], s[nt][3]));
        }
        mx0 = fmaxf(mx0, __shfl_xor_sync(0xffffffffu, mx0, 1));
        mx0 = fmaxf(mx0, __shfl_xor_sync(0xffffffffu, mx0, 2));
        mx1 = fmaxf(mx1, __shfl_xor_sync(0xffffffffu, mx1, 1));
        mx1 = fmaxf(mx1, __shfl_xor_sync(0xffffffffu, mx1, 2));

        const float mn0 = fmaxf(m0r, mx0);
        const float mn1 = fmaxf(m1r, mx1);
        const float sc0 = __expf(m0r - mn0);
        const float sc1 = __expf(m1r - mn1);
        m0r = mn0; m1r = mn1;

        float rs0 = 0.f, rs1 = 0.f;
#pragma unroll
        for (int nt = 0; nt < 8; nt++) {
            s[nt][0] = __expf(s[nt][0] - mn0); rs0 += s[nt][0];
            s[nt][1] = __expf(s[nt][1] - mn0); rs0 += s[nt][1];
            s[nt][2] = __expf(s[nt][2] - mn1); rs1 += s[nt][2];
            s[nt][3] = __expf(s[nt][3] - mn1); rs1 += s[nt][3];
        }
        rs0 += __shfl_xor_sync(0xffffffffu, rs0, 1);
        rs0 += __shfl_xor_sync(0xffffffffu, rs0, 2);
        rs1 += __shfl_xor_sync(0xffffffffu, rs1, 1);
        rs1 += __shfl_xor_sync(0xffffffffu, rs1, 2);
        l0r = l0r*sc0 + rs0;
        l1r = l1r*sc1 + rs1;

#pragma unroll
        for (int nt = 0; nt < 16; nt++) {
            o[nt][0] *= sc0; o[nt][1] *= sc0;
            o[nt][2] *= sc1; o[nt][3] *= sc1;
        }

        // ---- O += P V ----
#pragma unroll
        for (int kc4 = 0; kc4 < 4; kc4++) {
            uint32_t aPh[4], aPl[4];
#pragma unroll
            for (int hh = 0; hh < 2; hh++) {
                const float pe0 = s[2*kc4+hh][0], po0 = s[2*kc4+hh][1];
                const float pe1 = s[2*kc4+hh][2], po1 = s[2*kc4+hh][3];
                const uint32_t ph0 = pack_bf16x2(pe0, po0);
                const uint32_t ph1 = pack_bf16x2(pe1, po1);
                aPh[2*hh]   = ph0;
                aPh[2*hh+1] = ph1;
                __nv_bfloat162 b0 = *(const __nv_bfloat162*)&ph0;
                __nv_bfloat162 b1 = *(const __nv_bfloat162*)&ph1;
                aPl[2*hh]   = pack_bf16x2(pe0 - __bfloat162float(b0.x),
                                          po0 - __bfloat162float(b0.y));
                aPl[2*hh+1] = pack_bf16x2(pe1 - __bfloat162float(b1.x),
                                          po1 - __bfloat162float(b1.y));
            }
#pragma unroll
            for (int ntp = 0; ntp < 8; ntp++) {
                uint32_t vH[4], vL[4];
                const uint32_t vo = voff4 + (uint32_t)(kc4*(16*FSTR*2)) + ntp*32;
                ldmat4t(vH, aVh + vo);
                ldmat4t(vL, aVl + vo);
                mma16816(o[2*ntp],   aPh, vH[0], vH[1]);
                mma16816(o[2*ntp+1], aPh, vH[2], vH[3]);
                mma16816(o[2*ntp],   aPh, vL[0], vL[1]);
                mma16816(o[2*ntp+1], aPh, vL[2], vL[3]);
                mma16816(o[2*ntp],   aPl, vH[0], vH[1]);
                mma16816(o[2*ntp+1], aPl, vH[2], vH[3]);
            }
        }
    }

    const float li0 = 1.f / l0r, li1 = 1.f / l1r;
    const int rg = q0 + r0;
    const int cb = 2*(lane & 3);
#pragma unroll
    for (int nt = 0; nt < 16; nt++) {
        const int col = nt*8 + cb;
        *(float2*)&out[base + (size_t)rg*H_ + col] =
            make_float2(o[nt][0]*li0, o[nt][1]*li0);
        *(float2*)&out[base + (size_t)(rg+8)*H_ + col] =
            make_float2(o[nt][2]*li1, o[nt][3]*li1);
    }
}

// ---------------------------------------------------------------------------
extern "C" void kernel_launch(void* const* d_in, const int* in_sizes, int n_in,
                              void* d_out, int out_size)
{
    (void)in_sizes; (void)n_in; (void)out_size;
    const float* x  = (const float*)d_in[0];
    const float* Wq = (const float*)d_in[1];
    const float* Wk = (const float*)d_in[2];
    const float* Wv = (const float*)d_in[3];
    float* out = (float*)d_out;

    convert_w_kernel<<<dim3((D_*H_)/256, 3), 256>>>(Wq, Wk, Wv);

    cudaFuncSetAttribute(proj_hmma3_kernel,
                         cudaFuncAttributeMaxDynamicSharedMemorySize, PX_SMEM);
    proj_hmma3_kernel<<<M_/128, 256, PX_SMEM>>>(x);

    cudaFuncSetAttribute(flash3_kernel,
                         cudaFuncAttributeMaxDynamicSharedMemorySize, FSMEM);
    flash3_kernel<<<dim3(16, B_), 256, FSMEM>>>(out);
}

// round 13
// speedup vs baseline: 4.2701x; 1.0854x over previous
#include <cuda_runtime.h>
#include <cuda_fp16.h>
#include <math.h>
#include <stdint.h>

#define B_ 8
#define T_ 2048
#define D_ 2048
#define H_ 128
#define M_ (B_*T_)

// Scratch (alloc-free rules: __device__ globals)
__device__ __half g_qhi[M_*H_], g_qlo[M_*H_];   // q pre-scaled by sqrt(128)
__device__ __half g_khi[M_*H_], g_klo[M_*H_];
__device__ __half g_vhi[M_*H_], g_vlo[M_*H_];
__device__ __half g_wthi[3][H_*D_];             // W^T: [n][k], weight-major
__device__ __half g_wtlo[3][H_*D_];

// ---------------------------------------------------------------------------
// helpers
// ---------------------------------------------------------------------------
__device__ __forceinline__ uint32_t smem_u32(const void* p) {
    uint32_t a;
    asm("{ .reg .u64 t; cvta.to.shared.u64 t, %1; cvt.u32.u64 %0, t; }" : "=r"(a) : "l"(p));
    return a;
}
__device__ __forceinline__ void ldmat4(uint32_t* r, uint32_t addr) {
    asm volatile("ldmatrix.sync.aligned.m8n8.x4.shared.b16 {%0,%1,%2,%3}, [%4];"
        : "=r"(r[0]), "=r"(r[1]), "=r"(r[2]), "=r"(r[3]) : "r"(addr));
}
__device__ __forceinline__ void ldmat4t(uint32_t* r, uint32_t addr) {
    asm volatile("ldmatrix.sync.aligned.m8n8.x4.trans.shared.b16 {%0,%1,%2,%3}, [%4];"
        : "=r"(r[0]), "=r"(r[1]), "=r"(r[2]), "=r"(r[3]) : "r"(addr));
}
__device__ __forceinline__ void mma16816(float* d, const uint32_t* a,
                                         uint32_t b0, uint32_t b1) {
    asm volatile(
        "mma.sync.aligned.m16n8k16.row.col.f32.f16.f16.f32 "
        "{%0,%1,%2,%3}, {%4,%5,%6,%7}, {%8,%9}, {%0,%1,%2,%3};"
        : "+f"(d[0]), "+f"(d[1]), "+f"(d[2]), "+f"(d[3])
        : "r"(a[0]), "r"(a[1]), "r"(a[2]), "r"(a[3]), "r"(b0), "r"(b1));
}
// packs (even -> low half, odd -> high half)
__device__ __forceinline__ uint32_t pack_f16x2(float even, float odd) {
    uint32_t r;
    asm("cvt.rn.f16x2.f32 %0, %1, %2;" : "=r"(r) : "f"(odd), "f"(even));
    return r;
}
#define CP_ASYNC16(dst, src) \
    asm volatile("cp.async.cg.shared.global [%0], [%1], 16;" :: "r"(dst), "l"(src))
#define CP_COMMIT() asm volatile("cp.async.commit_group;" ::: "memory")
#define CP_WAIT0()  asm volatile("cp.async.wait_group 0;" ::: "memory")

// ---------------------------------------------------------------------------
// W convert: fp32 -> fp16 hi + lo, transposed [n][k]
// ---------------------------------------------------------------------------
__global__ __launch_bounds__(256) void convert_w_kernel(
    const float* __restrict__ Wq, const float* __restrict__ Wk, const float* __restrict__ Wv)
{
    const int w = blockIdx.y;
    const float* W = (w == 0) ? Wq : (w == 1) ? Wk : Wv;
    const int e = blockIdx.x * 256 + threadIdx.x;
    const int k = e >> 7, n = e & 127;
    float v = W[(size_t)k * H_ + n];
    __half h = __float2half_rn(v);
    __half l = __float2half_rn(v - __half2float(h));
    g_wthi[w][(size_t)n * D_ + k] = h;
    g_wtlo[w][(size_t)n * D_ + k] = l;
}

// ---------------------------------------------------------------------------
// Projection: CTA = 128 rows x 384 cols (all 3 weights), grid 128.
// fp16 splits. q,k: hh+hl+lh. v (cols>=256): hh+hl only (lo-x term dropped).
// ---------------------------------------------------------------------------
#define PX_RAW(buf) ((buf)*18432u)                  // 128 x 144B fp32 raw A
#define PX_AHI(buf) (36864u + (buf)*20480u)         // 128x40 f16 hi (stride 80B)
#define PX_ALO(buf) (PX_AHI(buf) + 10240u)
#define PX_BHI(buf) (77824u + (buf)*61440u)         // 384x40 f16 hi (stride 80B)
#define PX_BLO(buf) (PX_BHI(buf) + 30720u)
#define PX_SMEM     200704

__global__ __launch_bounds__(256, 1) void proj_hmma3_kernel(const float* __restrict__ x)
{
    extern __shared__ char psm[];
    const uint32_t s0 = smem_u32(psm);

    const int t    = threadIdx.x;
    const int lane = t & 31;
    const int wid  = t >> 5;
    const int wm   = wid & 1;        // M half
    const int wn   = wid >> 1;       // N quarter (96 cols)
    const int m0   = blockIdx.x * 128;

    const __half* WT_hi = &g_wthi[0][0];
    const __half* WT_lo = &g_wtlo[0][0];

    float acc[4][12][4];
#pragma unroll
    for (int mt = 0; mt < 4; mt++)
#pragma unroll
        for (int nt = 0; nt < 12; nt++)
#pragma unroll
            for (int e = 0; e < 4; e++) acc[mt][nt][e] = 0.f;

    const int arow = t >> 1;
    const int ac0  = (t & 1) * 4;

    const uint32_t aoff = (uint32_t)(((wm*64 + (lane & 15))*40 + (lane >> 4)*8) * 2);
    const uint32_t boff = (uint32_t)(((wn*96 + (lane & 7) + ((lane >> 4) & 1)*8)*40
                                      + ((lane >> 3) & 1)*8) * 2);

    // prologue: issue chunk 0
    {
#pragma unroll
        for (int i = 0; i < 4; i++) {
            const int c = ac0 + i;
            CP_ASYNC16(s0 + PX_RAW(0) + (uint32_t)(arow*144 + c*16),
                       x + (size_t)(m0 + arow) * D_ + c*4);
        }
#pragma unroll
        for (int i = 0; i < 6; i++) {
            const int idx = t + i*256;
            const int n = idx >> 2, c = idx & 3;
            CP_ASYNC16(s0 + PX_BHI(0) + (uint32_t)(n*80 + c*16),
                       WT_hi + (size_t)n * D_ + c*8);
            CP_ASYNC16(s0 + PX_BLO(0) + (uint32_t)(n*80 + c*16),
                       WT_lo + (size_t)n * D_ + c*8);
        }
        CP_COMMIT();
    }

    for (int ch = 0; ch < 64; ch++) {
        const int buf = ch & 1;

        CP_WAIT0();
        __syncthreads();

        // convert A raw fp32 -> f16 hi/lo
        {
            const int row = t >> 1, half = t & 1;
            const char* rsrc = psm + PX_RAW(buf) + row*144 + half*64;
            char* dhi = psm + PX_AHI(buf) + (row*40 + half*16)*2;
            char* dlo = psm + PX_ALO(buf) + (row*40 + half*16)*2;
#pragma unroll
            for (int j = 0; j < 4; j++) {
                float4 v = *(const float4*)(rsrc + j*16);
                uint32_t h01 = pack_f16x2(v.x, v.y);
                uint32_t h23 = pack_f16x2(v.z, v.w);
                __half2 b01 = *(const __half2*)&h01;
                __half2 b23 = *(const __half2*)&h23;
                uint32_t l01 = pack_f16x2(v.x - __half2float(b01.x),
                                          v.y - __half2float(b01.y));
                uint32_t l23 = pack_f16x2(v.z - __half2float(b23.x),
                                          v.w - __half2float(b23.y));
                *(uint32_t*)(dhi + j*8)     = h01;
                *(uint32_t*)(dhi + j*8 + 4) = h23;
                *(uint32_t*)(dlo + j*8)     = l01;
                *(uint32_t*)(dlo + j*8 + 4) = l23;
            }
        }
        __syncthreads();

        // issue chunk ch+1 (interleaves with MMA)
        if (ch < 63) {
            const int nbuf = buf ^ 1;
            const int k0 = (ch + 1) * 32;
#pragma unroll
            for (int i = 0; i < 4; i++) {
                const int c = ac0 + i;
                CP_ASYNC16(s0 + PX_RAW(nbuf) + (uint32_t)(arow*144 + c*16),
                           x + (size_t)(m0 + arow) * D_ + k0 + c*4);
            }
#pragma unroll
            for (int i = 0; i < 6; i++) {
                const int idx = t + i*256;
                const int n = idx >> 2, c = idx & 3;
                CP_ASYNC16(s0 + PX_BHI(nbuf) + (uint32_t)(n*80 + c*16),
                           WT_hi + (size_t)n * D_ + k0 + c*8);
                CP_ASYNC16(s0 + PX_BLO(nbuf) + (uint32_t)(n*80 + c*16),
                           WT_lo + (size_t)n * D_ + k0 + c*8);
            }
            CP_COMMIT();
        }

        // compute chunk ch
        const uint32_t abase_h = s0 + PX_AHI(buf) + aoff;
        const uint32_t abase_l = s0 + PX_ALO(buf) + aoff;
        const uint32_t bbase_h = s0 + PX_BHI(buf) + boff;
        const uint32_t bbase_l = s0 + PX_BLO(buf) + boff;
#pragma unroll
        for (int ks = 0; ks < 2; ks++) {
            uint32_t a[4][4];
            // pass 1: A = hi -> hh + hl (all weights)
#pragma unroll
            for (int mt = 0; mt < 4; mt++)
                ldmat4(a[mt], abase_h + (uint32_t)(mt*1280 + ks*32));
#pragma unroll
            for (int np = 0; np < 6; np++) {
                uint32_t bh[4], bl[4];
                ldmat4(bh, bbase_h + (uint32_t)(np*1280 + ks*32));
                ldmat4(bl, bbase_l + (uint32_t)(np*1280 + ks*32));
#pragma unroll
                for (int mt = 0; mt < 4; mt++) {
                    mma16816(acc[mt][2*np],   a[mt], bh[0], bh[1]);
                    mma16816(acc[mt][2*np+1], a[mt], bh[2], bh[3]);
                }
#pragma unroll
                for (int mt = 0; mt < 4; mt++) {
                    mma16816(acc[mt][2*np],   a[mt], bl[0], bl[1]);
                    mma16816(acc[mt][2*np+1], a[mt], bl[2], bl[3]);
                }
            }
            // pass 2: A = lo -> lh, only for q,k columns (global col < 256)
            if (wn < 3) {
#pragma unroll
                for (int mt = 0; mt < 4; mt++)
                    ldmat4(a[mt], abase_l + (uint32_t)(mt*1280 + ks*32));
#pragma unroll
                for (int np = 0; np < 6; np++) {
                    if (wn*96 + np*16 < 256) {
                        uint32_t bh[4];
                        ldmat4(bh, bbase_h + (uint32_t)(np*1280 + ks*32));
#pragma unroll
                        for (int mt = 0; mt < 4; mt++) {
                            mma16816(acc[mt][2*np],   a[mt], bh[0], bh[1]);
                            mma16816(acc[mt][2*np+1], a[mt], bh[2], bh[3]);
                        }
                    }
                }
            }
        }
    }

    // epilogue: split to f16 hi/lo, q scaled by sqrt(128)
    const int dr = lane >> 2;
    const int dc = (lane & 3) * 2;
#pragma unroll
    for (int mt = 0; mt < 4; mt++) {
#pragma unroll
        for (int nt = 0; nt < 12; nt++) {
            const int cg  = wn*96 + nt*8 + dc;
            const int w   = cg >> 7;
            const int col = cg & 127;
            __half* ohi = (w == 0) ? g_qhi : (w == 1) ? g_khi : g_vhi;
            __half* olo = (w == 0) ? g_qlo : (w == 1) ? g_klo : g_vlo;
            const float sc = (w == 0) ? 11.313708498984761f : 1.0f;
            const int row = m0 + wm*64 + mt*16 + dr;
#pragma unroll
            for (int half = 0; half < 2; half++) {
                const int rr = row + half*8;
                float v0 = acc[mt][nt][half*2 + 0] * sc;
                float v1 = acc[mt][nt][half*2 + 1] * sc;
                uint32_t h = pack_f16x2(v0, v1);
                __half2 bh = *(const __half2*)&h;
                uint32_t l = pack_f16x2(v0 - __half2float(bh.x),
                                        v1 - __half2float(bh.y));
                *(uint32_t*)(ohi + (size_t)rr * H_ + col) = h;
                *(uint32_t*)(olo + (size_t)rr * H_ + col) = l;
            }
        }
    }
}

// ---------------------------------------------------------------------------
// Flash attention v4 — fp16 HMMA FA2.
// S: hh + hl + lh (fp16 -> 2^-21 quality). PV: Ph*Vh + Ph*Vl (Pl dropped).
// ---------------------------------------------------------------------------
#define FSTR 136
#define FQH  (64*FSTR)
#define FGRP (6*FQH)
#define FSMEM (2*FGRP*2)

__global__ __launch_bounds__(256) void flash4_kernel(float* __restrict__ out)
{
    extern __shared__ __half fsm[];
    const int t    = threadIdx.x;
    const int g    = t >> 7;
    const int gt   = t & 127;
    const int warp = gt >> 5;
    const int lane = t & 31;
    const int b    = blockIdx.y;
    const int p    = blockIdx.x;
    const int qb   = g ? p : (31 - p);
    const int q0   = qb * 64;
    const size_t base = (size_t)b * T_ * H_;

    __half* sQh = fsm + g*FGRP;
    __half* sQl = sQh + FQH;
    __half* sKh = sQl + FQH;
    __half* sKl = sKh + FQH;
    __half* sVh = sKl + FQH;
    __half* sVl = sVh + FQH;
    const uint32_t aQh = smem_u32(sQh), aQl = smem_u32(sQl);
    const uint32_t aKh = smem_u32(sKh), aKl = smem_u32(sKl);
    const uint32_t aVh = smem_u32(sVh), aVl = smem_u32(sVl);

#pragma unroll
    for (int i = 0; i < 8; i++) {
        const int idx = gt + i*128;
        const int row = idx >> 4, c = idx & 15;
        const size_t go = base + (size_t)(q0 + row)*H_ + c*8;
        *(uint4*)(sQh + row*FSTR + c*8) = *(const uint4*)(g_qhi + go);
        *(uint4*)(sQl + row*FSTR + c*8) = *(const uint4*)(g_qlo + go);
    }

    float o[16][4];
#pragma unroll
    for (int nt = 0; nt < 16; nt++)
#pragma unroll
        for (int e = 0; e < 4; e++) o[nt][e] = 0.f;
    float m0r = -1e30f, m1r = -1e30f, l0r = 0.f, l1r = 0.f;

    const uint32_t aoff = (uint32_t)(((warp*16 + (lane & 15))*FSTR + (lane >> 4)*8) * 2);
    const uint32_t boff = (uint32_t)((((lane & 7) + ((lane >> 4) & 1)*8)*FSTR
                                      + ((lane >> 3) & 1)*8) * 2);
    const uint32_t voff4 = (uint32_t)(((lane & 15)*FSTR)*2 + (lane >> 4)*16);

    const int r0 = warp*16 + (lane >> 2);

    for (int kb = 0; kb <= qb; kb++) {
        const int k0 = kb * 64;
        asm volatile("bar.sync %0, %1;" :: "r"(g+1), "r"(128) : "memory");

#pragma unroll
        for (int i = 0; i < 8; i++) {
            const int idx = gt + i*128;
            const int row = idx >> 4, c = idx & 15;
            const size_t go = base + (size_t)(k0 + row)*H_ + c*8;
            *(uint4*)(sKh + row*FSTR + c*8) = *(const uint4*)(g_khi + go);
            *(uint4*)(sKl + row*FSTR + c*8) = *(const uint4*)(g_klo + go);
            *(uint4*)(sVh + row*FSTR + c*8) = *(const uint4*)(g_vhi + go);
            *(uint4*)(sVl + row*FSTR + c*8) = *(const uint4*)(g_vlo + go);
        }
        asm volatile("bar.sync %0, %1;" :: "r"(g+1), "r"(128) : "memory");

        // ---- S = Q K^T : hh + hl + lh ----
        float s[8][4];
#pragma unroll
        for (int nt = 0; nt < 8; nt++)
#pragma unroll
            for (int e = 0; e < 4; e++) s[nt][e] = 0.f;

#pragma unroll
        for (int kc = 0; kc < 8; kc++) {
            uint32_t aH[4], aL[4];
            ldmat4(aH, aQh + aoff + kc*32);
            ldmat4(aL, aQl + aoff + kc*32);
#pragma unroll
            for (int ntp = 0; ntp < 4; ntp++) {
                uint32_t bH[4], bL[4];
                const uint32_t bo = boff + (uint32_t)(ntp*(16*FSTR*2)) + kc*32;
                ldmat4(bH, aKh + bo);
                ldmat4(bL, aKl + bo);
#pragma unroll
                for (int h = 0; h < 2; h++) {
                    const int nt = ntp*2 + h;
                    mma16816(s[nt], aH, bH[2*h], bH[2*h+1]);
                    mma16816(s[nt], aH, bL[2*h], bL[2*h+1]);
                    mma16816(s[nt], aL, bH[2*h], bH[2*h+1]);
                }
            }
        }

        if (kb == qb) {
#pragma unroll
            for (int nt = 0; nt < 8; nt++) {
                const int c0 = nt*8 + 2*(lane & 3);
                if (c0     > r0)     s[nt][0] = -1e9f;
                if (c0 + 1 > r0)     s[nt][1] = -1e9f;
                if (c0     > r0 + 8) s[nt][2] = -1e9f;
                if (c0 + 1 > r0 + 8) s[nt][3] = -1e9f;
            }
        }

        float mx0 = -1e30f, mx1 = -1e30f;
#pragma unroll
        for (int nt = 0; nt < 8; nt++) {
            mx0 = fmaxf(mx0, fmaxf(s[nt][0], s[nt][1]));
            mx1 = fmaxf(mx1, fmaxf(s[nt][2], s[nt][3]));
        }
        mx0 = fmaxf(mx0, __shfl_xor_sync(0xffffffffu, mx0, 1));
        mx0 = fmaxf(mx0, __shfl_xor_sync(0xffffffffu, mx0, 2));
        mx1 = fmaxf(mx1, __shfl_xor_sync(0xffffffffu, mx1, 1));
        mx1 = fmaxf(mx1, __shfl_xor_sync(0xffffffffu, mx1, 2));

        const float mn0 = fmaxf(m0r, mx0);
        const float mn1 = fmaxf(m1r, mx1);
        const float sc0 = __expf(m0r - mn0);
        const float sc1 = __expf(m1r - mn1);
        m0r = mn0; m1r = mn1;

        float rs0 = 0.f, rs1 = 0.f;
#pragma unroll
        for (int nt = 0; nt < 8; nt++) {
            s[nt][0] = __expf(s[nt][0] - mn0); rs0 += s[nt][0];
            s[nt][1] = __expf(s[nt][1] - mn0); rs0 += s[nt][1];
            s[nt][2] = __expf(s[nt][2] - mn1); rs1 += s[nt][2];
            s[nt][3] = __expf(s[nt][3] - mn1); rs1 += s[nt][3];
        }
        rs0 += __shfl_xor_sync(0xffffffffu, rs0, 1);
        rs0 += __shfl_xor_sync(0xffffffffu, rs0, 2);
        rs1 += __shfl_xor_sync(0xffffffffu, rs1, 1);
        rs1 += __shfl_xor_sync(0xffffffffu, rs1, 2);
        l0r = l0r*sc0 + rs0;
        l1r = l1r*sc1 + rs1;

#pragma unroll
        for (int nt = 0; nt < 16; nt++) {
            o[nt][0] *= sc0; o[nt][1] *= sc0;
            o[nt][2] *= sc1; o[nt][3] *= sc1;
        }

        // ---- O += P V : Ph*Vh + Ph*Vl (fp16 P, lo-P dropped) ----
#pragma unroll
        for (int kc4 = 0; kc4 < 4; kc4++) {
            uint32_t aPh[4];
#pragma unroll
            for (int hh = 0; hh < 2; hh++) {
                aPh[2*hh]   = pack_f16x2(s[2*kc4+hh][0], s[2*kc4+hh][1]);
                aPh[2*hh+1] = pack_f16x2(s[2*kc4+hh][2], s[2*kc4+hh][3]);
            }
#pragma unroll
            for (int ntp = 0; ntp < 8; ntp++) {
                uint32_t vH[4], vL[4];
                const uint32_t vo = voff4 + (uint32_t)(kc4*(16*FSTR*2)) + ntp*32;
                ldmat4t(vH, aVh + vo);
                ldmat4t(vL, aVl + vo);
                mma16816(o[2*ntp],   aPh, vH[0], vH[1]);
                mma16816(o[2*ntp+1], aPh, vH[2], vH[3]);
                mma16816(o[2*ntp],   aPh, vL[0], vL[1]);
                mma16816(o[2*ntp+1], aPh, vL[2], vL[3]);
            }
        }
    }

    const float li0 = 1.f / l0r, li1 = 1.f / l1r;
    const int rg = q0 + r0;
    const int cb = 2*(lane & 3);
#pragma unroll
    for (int nt = 0; nt < 16; nt++) {
        const int col = nt*8 + cb;
        *(float2*)&out[base + (size_t)rg*H_ + col] =
            make_float2(o[nt][0]*li0, o[nt][1]*li0);
        *(float2*)&out[base + (size_t)(rg+8)*H_ + col] =
            make_float2(o[nt][2]*li1, o[nt][3]*li1);
    }
}

// ---------------------------------------------------------------------------
extern "C" void kernel_launch(void* const* d_in, const int* in_sizes, int n_in,
                              void* d_out, int out_size)
{
    (void)in_sizes; (void)n_in; (void)out_size;
    const float* x  = (const float*)d_in[0];
    const float* Wq = (const float*)d_in[1];
    const float* Wk = (const float*)d_in[2];
    const float* Wv = (const float*)d_in[3];
    float* out = (float*)d_out;

    convert_w_kernel<<<dim3((D_*H_)/256, 3), 256>>>(Wq, Wk, Wv);

    cudaFuncSetAttribute(proj_hmma3_kernel,
                         cudaFuncAttributeMaxDynamicSharedMemorySize, PX_SMEM);
    proj_hmma3_kernel<<<M_/128, 256, PX_SMEM>>>(x);

    cudaFuncSetAttribute(flash4_kernel,
                         cudaFuncAttributeMaxDynamicSharedMemorySize, FSMEM);
    flash4_kernel<<<dim3(16, B_), 256, FSMEM>>>(out);
}

// round 14
// speedup vs baseline: 4.6661x; 1.0927x over previous
#include <cuda_runtime.h>
#include <cuda_fp16.h>
#include <math.h>
#include <stdint.h>

#define B_ 8
#define T_ 2048
#define D_ 2048
#define H_ 128
#define M_ (B_*T_)

// Scratch (alloc-free rules: __device__ globals)
__device__ __half g_qhi[M_*H_], g_qlo[M_*H_];   // q pre-scaled by sqrt(128)
__device__ __half g_khi[M_*H_], g_klo[M_*H_];
__device__ __half g_vhi[M_*H_];                 // v: plain fp16 (lo terms dropped)
__device__ __half g_wthi[3][H_*D_];             // W^T: [n][k], weight-major
__device__ __half g_wtlo[3][H_*D_];

// ---------------------------------------------------------------------------
// helpers
// ---------------------------------------------------------------------------
__device__ __forceinline__ uint32_t smem_u32(const void* p) {
    uint32_t a;
    asm("{ .reg .u64 t; cvta.to.shared.u64 t, %1; cvt.u32.u64 %0, t; }" : "=r"(a) : "l"(p));
    return a;
}
__device__ __forceinline__ void ldmat4(uint32_t* r, uint32_t addr) {
    asm volatile("ldmatrix.sync.aligned.m8n8.x4.shared.b16 {%0,%1,%2,%3}, [%4];"
        : "=r"(r[0]), "=r"(r[1]), "=r"(r[2]), "=r"(r[3]) : "r"(addr));
}
__device__ __forceinline__ void ldmat4t(uint32_t* r, uint32_t addr) {
    asm volatile("ldmatrix.sync.aligned.m8n8.x4.trans.shared.b16 {%0,%1,%2,%3}, [%4];"
        : "=r"(r[0]), "=r"(r[1]), "=r"(r[2]), "=r"(r[3]) : "r"(addr));
}
__device__ __forceinline__ void mma16816(float* d, const uint32_t* a,
                                         uint32_t b0, uint32_t b1) {
    asm volatile(
        "mma.sync.aligned.m16n8k16.row.col.f32.f16.f16.f32 "
        "{%0,%1,%2,%3}, {%4,%5,%6,%7}, {%8,%9}, {%0,%1,%2,%3};"
        : "+f"(d[0]), "+f"(d[1]), "+f"(d[2]), "+f"(d[3])
        : "r"(a[0]), "r"(a[1]), "r"(a[2]), "r"(a[3]), "r"(b0), "r"(b1));
}
__device__ __forceinline__ uint32_t pack_f16x2(float even, float odd) {
    uint32_t r;
    asm("cvt.rn.f16x2.f32 %0, %1, %2;" : "=r"(r) : "f"(odd), "f"(even));
    return r;
}
#define CP_ASYNC16(dst, src) \
    asm volatile("cp.async.cg.shared.global [%0], [%1], 16;" :: "r"(dst), "l"(src))
#define CP_COMMIT() asm volatile("cp.async.commit_group;" ::: "memory")
#define CP_WAIT0()  asm volatile("cp.async.wait_group 0;" ::: "memory")

// ---------------------------------------------------------------------------
// W convert: fp32 -> fp16 hi + lo, transposed [n][k]
// ---------------------------------------------------------------------------
__global__ __launch_bounds__(256) void convert_w_kernel(
    const float* __restrict__ Wq, const float* __restrict__ Wk, const float* __restrict__ Wv)
{
    const int w = blockIdx.y;
    const float* W = (w == 0) ? Wq : (w == 1) ? Wk : Wv;
    const int e = blockIdx.x * 256 + threadIdx.x;
    const int k = e >> 7, n = e & 127;
    float v = W[(size_t)k * H_ + n];
    __half h = __float2half_rn(v);
    __half l = __float2half_rn(v - __half2float(h));
    g_wthi[w][(size_t)n * D_ + k] = h;
    g_wtlo[w][(size_t)n * D_ + k] = l;
}

// ---------------------------------------------------------------------------
// Projection: CTA = 128 rows x 384 cols (all 3 weights), grid 128.
// fp16 splits. q,k (cols<256): hh+hl+lh.  v (cols>=256): hh only.
// ---------------------------------------------------------------------------
#define PX_RAW(buf) ((buf)*18432u)                  // 128 x 144B fp32 raw A
#define PX_AHI(buf) (36864u + (buf)*20480u)         // 128x40 f16 hi (stride 80B)
#define PX_ALO(buf) (PX_AHI(buf) + 10240u)
#define PX_BHI(buf) (77824u + (buf)*61440u)         // 384x40 f16 hi (stride 80B)
#define PX_BLO(buf) (PX_BHI(buf) + 30720u)
#define PX_SMEM     200704

__global__ __launch_bounds__(256, 1) void proj_hmma3_kernel(const float* __restrict__ x)
{
    extern __shared__ char psm[];
    const uint32_t s0 = smem_u32(psm);

    const int t    = threadIdx.x;
    const int lane = t & 31;
    const int wid  = t >> 5;
    const int wm   = wid & 1;        // M half
    const int wn   = wid >> 1;       // N quarter (96 cols)
    const int m0   = blockIdx.x * 128;

    const __half* WT_hi = &g_wthi[0][0];
    const __half* WT_lo = &g_wtlo[0][0];

    float acc[4][12][4];
#pragma unroll
    for (int mt = 0; mt < 4; mt++)
#pragma unroll
        for (int nt = 0; nt < 12; nt++)
#pragma unroll
            for (int e = 0; e < 4; e++) acc[mt][nt][e] = 0.f;

    const int arow = t >> 1;
    const int ac0  = (t & 1) * 4;

    const uint32_t aoff = (uint32_t)(((wm*64 + (lane & 15))*40 + (lane >> 4)*8) * 2);
    const uint32_t boff = (uint32_t)(((wn*96 + (lane & 7) + ((lane >> 4) & 1)*8)*40
                                      + ((lane >> 3) & 1)*8) * 2);

    // prologue: issue chunk 0
    {
#pragma unroll
        for (int i = 0; i < 4; i++) {
            const int c = ac0 + i;
            CP_ASYNC16(s0 + PX_RAW(0) + (uint32_t)(arow*144 + c*16),
                       x + (size_t)(m0 + arow) * D_ + c*4);
        }
#pragma unroll
        for (int i = 0; i < 6; i++) {
            const int idx = t + i*256;
            const int n = idx >> 2, c = idx & 3;
            CP_ASYNC16(s0 + PX_BHI(0) + (uint32_t)(n*80 + c*16),
                       WT_hi + (size_t)n * D_ + c*8);
            CP_ASYNC16(s0 + PX_BLO(0) + (uint32_t)(n*80 + c*16),
                       WT_lo + (size_t)n * D_ + c*8);
        }
        CP_COMMIT();
    }

    for (int ch = 0; ch < 64; ch++) {
        const int buf = ch & 1;

        CP_WAIT0();
        __syncthreads();

        // convert A raw fp32 -> f16 hi/lo
        {
            const int row = t >> 1, half = t & 1;
            const char* rsrc = psm + PX_RAW(buf) + row*144 + half*64;
            char* dhi = psm + PX_AHI(buf) + (row*40 + half*16)*2;
            char* dlo = psm + PX_ALO(buf) + (row*40 + half*16)*2;
#pragma unroll
            for (int j = 0; j < 4; j++) {
                float4 v = *(const float4*)(rsrc + j*16);
                uint32_t h01 = pack_f16x2(v.x, v.y);
                uint32_t h23 = pack_f16x2(v.z, v.w);
                __half2 b01 = *(const __half2*)&h01;
                __half2 b23 = *(const __half2*)&h23;
                uint32_t l01 = pack_f16x2(v.x - __half2float(b01.x),
                                          v.y - __half2float(b01.y));
                uint32_t l23 = pack_f16x2(v.z - __half2float(b23.x),
                                          v.w - __half2float(b23.y));
                *(uint32_t*)(dhi + j*8)     = h01;
                *(uint32_t*)(dhi + j*8 + 4) = h23;
                *(uint32_t*)(dlo + j*8)     = l01;
                *(uint32_t*)(dlo + j*8 + 4) = l23;
            }
        }
        __syncthreads();

        // issue chunk ch+1 (interleaves with MMA)
        if (ch < 63) {
            const int nbuf = buf ^ 1;
            const int k0 = (ch + 1) * 32;
#pragma unroll
            for (int i = 0; i < 4; i++) {
                const int c = ac0 + i;
                CP_ASYNC16(s0 + PX_RAW(nbuf) + (uint32_t)(arow*144 + c*16),
                           x + (size_t)(m0 + arow) * D_ + k0 + c*4);
            }
#pragma unroll
            for (int i = 0; i < 6; i++) {
                const int idx = t + i*256;
                const int n = idx >> 2, c = idx & 3;
                CP_ASYNC16(s0 + PX_BHI(nbuf) + (uint32_t)(n*80 + c*16),
                           WT_hi + (size_t)n * D_ + k0 + c*8);
                CP_ASYNC16(s0 + PX_BLO(nbuf) + (uint32_t)(n*80 + c*16),
                           WT_lo + (size_t)n * D_ + k0 + c*8);
            }
            CP_COMMIT();
        }

        // compute chunk ch
        const uint32_t abase_h = s0 + PX_AHI(buf) + aoff;
        const uint32_t abase_l = s0 + PX_ALO(buf) + aoff;
        const uint32_t bbase_h = s0 + PX_BHI(buf) + boff;
        const uint32_t bbase_l = s0 + PX_BLO(buf) + boff;
#pragma unroll
        for (int ks = 0; ks < 2; ks++) {
            uint32_t a[4][4];
            // pass 1: A = hi -> hh (all cols) + hl (q,k cols only)
#pragma unroll
            for (int mt = 0; mt < 4; mt++)
                ldmat4(a[mt], abase_h + (uint32_t)(mt*1280 + ks*32));
#pragma unroll
            for (int np = 0; np < 6; np++) {
                uint32_t bh[4];
                ldmat4(bh, bbase_h + (uint32_t)(np*1280 + ks*32));
#pragma unroll
                for (int mt = 0; mt < 4; mt++) {
                    mma16816(acc[mt][2*np],   a[mt], bh[0], bh[1]);
                    mma16816(acc[mt][2*np+1], a[mt], bh[2], bh[3]);
                }
                if (wn*96 + np*16 < 256) {       // q,k only: hl term
                    uint32_t bl[4];
                    ldmat4(bl, bbase_l + (uint32_t)(np*1280 + ks*32));
#pragma unroll
                    for (int mt = 0; mt < 4; mt++) {
                        mma16816(acc[mt][2*np],   a[mt], bl[0], bl[1]);
                        mma16816(acc[mt][2*np+1], a[mt], bl[2], bl[3]);
                    }
                }
            }
            // pass 2: A = lo -> lh, q,k cols only
            if (wn < 3) {
#pragma unroll
                for (int mt = 0; mt < 4; mt++)
                    ldmat4(a[mt], abase_l + (uint32_t)(mt*1280 + ks*32));
#pragma unroll
                for (int np = 0; np < 6; np++) {
                    if (wn*96 + np*16 < 256) {
                        uint32_t bh[4];
                        ldmat4(bh, bbase_h + (uint32_t)(np*1280 + ks*32));
#pragma unroll
                        for (int mt = 0; mt < 4; mt++) {
                            mma16816(acc[mt][2*np],   a[mt], bh[0], bh[1]);
                            mma16816(acc[mt][2*np+1], a[mt], bh[2], bh[3]);
                        }
                    }
                }
            }
        }
    }

    // epilogue: q,k -> f16 hi/lo (q scaled by sqrt(128)); v -> f16 hi only
    const int dr = lane >> 2;
    const int dc = (lane & 3) * 2;
#pragma unroll
    for (int mt = 0; mt < 4; mt++) {
#pragma unroll
        for (int nt = 0; nt < 12; nt++) {
            const int cg  = wn*96 + nt*8 + dc;
            const int w   = cg >> 7;
            const int col = cg & 127;
            const int row = m0 + wm*64 + mt*16 + dr;
            if (w == 2) {
#pragma unroll
                for (int half = 0; half < 2; half++) {
                    const int rr = row + half*8;
                    uint32_t h = pack_f16x2(acc[mt][nt][half*2 + 0],
                                            acc[mt][nt][half*2 + 1]);
                    *(uint32_t*)(g_vhi + (size_t)rr * H_ + col) = h;
                }
            } else {
                __half* ohi = (w == 0) ? g_qhi : g_khi;
                __half* olo = (w == 0) ? g_qlo : g_klo;
                const float sc = (w == 0) ? 11.313708498984761f : 1.0f;
#pragma unroll
                for (int half = 0; half < 2; half++) {
                    const int rr = row + half*8;
                    float v0 = acc[mt][nt][half*2 + 0] * sc;
                    float v1 = acc[mt][nt][half*2 + 1] * sc;
                    uint32_t h = pack_f16x2(v0, v1);
                    __half2 bh = *(const __half2*)&h;
                    uint32_t l = pack_f16x2(v0 - __half2float(bh.x),
                                            v1 - __half2float(bh.y));
                    *(uint32_t*)(ohi + (size_t)rr * H_ + col) = h;
                    *(uint32_t*)(olo + (size_t)rr * H_ + col) = l;
                }
            }
        }
    }
}

// ---------------------------------------------------------------------------
// Flash attention v5 — fp16 HMMA FA2.
// S: hh + hl + lh.  PV: Ph*Vh only (V pure fp16).
// Components per group: Qh, Ql, Kh, Kl, Vh  (5).
// ---------------------------------------------------------------------------
#define FSTR 136
#define FQH  (64*FSTR)
#define FGRP (5*FQH)
#define FSMEM (2*FGRP*2)

__global__ __launch_bounds__(256) void flash5_kernel(float* __restrict__ out)
{
    extern __shared__ __half fsm[];
    const int t    = threadIdx.x;
    const int g    = t >> 7;
    const int gt   = t & 127;
    const int warp = gt >> 5;
    const int lane = t & 31;
    const int b    = blockIdx.y;
    const int p    = blockIdx.x;
    const int qb   = g ? p : (31 - p);
    const int q0   = qb * 64;
    const size_t base = (size_t)b * T_ * H_;

    __half* sQh = fsm + g*FGRP;
    __half* sQl = sQh + FQH;
    __half* sKh = sQl + FQH;
    __half* sKl = sKh + FQH;
    __half* sVh = sKl + FQH;
    const uint32_t aQh = smem_u32(sQh), aQl = smem_u32(sQl);
    const uint32_t aKh = smem_u32(sKh), aKl = smem_u32(sKl);
    const uint32_t aVh = smem_u32(sVh);

#pragma unroll
    for (int i = 0; i < 8; i++) {
        const int idx = gt + i*128;
        const int row = idx >> 4, c = idx & 15;
        const size_t go = base + (size_t)(q0 + row)*H_ + c*8;
        *(uint4*)(sQh + row*FSTR + c*8) = *(const uint4*)(g_qhi + go);
        *(uint4*)(sQl + row*FSTR + c*8) = *(const uint4*)(g_qlo + go);
    }

    float o[16][4];
#pragma unroll
    for (int nt = 0; nt < 16; nt++)
#pragma unroll
        for (int e = 0; e < 4; e++) o[nt][e] = 0.f;
    float m0r = -1e30f, m1r = -1e30f, l0r = 0.f, l1r = 0.f;

    const uint32_t aoff = (uint32_t)(((warp*16 + (lane & 15))*FSTR + (lane >> 4)*8) * 2);
    const uint32_t boff = (uint32_t)((((lane & 7) + ((lane >> 4) & 1)*8)*FSTR
                                      + ((lane >> 3) & 1)*8) * 2);
    const uint32_t voff4 = (uint32_t)(((lane & 15)*FSTR)*2 + (lane >> 4)*16);

    const int r0 = warp*16 + (lane >> 2);

    for (int kb = 0; kb <= qb; kb++) {
        const int k0 = kb * 64;
        asm volatile("bar.sync %0, %1;" :: "r"(g+1), "r"(128) : "memory");

#pragma unroll
        for (int i = 0; i < 8; i++) {
            const int idx = gt + i*128;
            const int row = idx >> 4, c = idx & 15;
            const size_t go = base + (size_t)(k0 + row)*H_ + c*8;
            *(uint4*)(sKh + row*FSTR + c*8) = *(const uint4*)(g_khi + go);
            *(uint4*)(sKl + row*FSTR + c*8) = *(const uint4*)(g_klo + go);
            *(uint4*)(sVh + row*FSTR + c*8) = *(const uint4*)(g_vhi + go);
        }
        asm volatile("bar.sync %0, %1;" :: "r"(g+1), "r"(128) : "memory");

        // ---- S = Q K^T : hh + hl + lh ----
        float s[8][4];
#pragma unroll
        for (int nt = 0; nt < 8; nt++)
#pragma unroll
            for (int e = 0; e < 4; e++) s[nt][e] = 0.f;

#pragma unroll
        for (int kc = 0; kc < 8; kc++) {
            uint32_t aH[4], aL[4];
            ldmat4(aH, aQh + aoff + kc*32);
            ldmat4(aL, aQl + aoff + kc*32);
#pragma unroll
            for (int ntp = 0; ntp < 4; ntp++) {
                uint32_t bH[4], bL[4];
                const uint32_t bo = boff + (uint32_t)(ntp*(16*FSTR*2)) + kc*32;
                ldmat4(bH, aKh + bo);
                ldmat4(bL, aKl + bo);
#pragma unroll
                for (int h = 0; h < 2; h++) {
                    const int nt = ntp*2 + h;
                    mma16816(s[nt], aH, bH[2*h], bH[2*h+1]);
                    mma16816(s[nt], aH, bL[2*h], bL[2*h+1]);
                    mma16816(s[nt], aL, bH[2*h], bH[2*h+1]);
                }
            }
        }

        if (kb == qb) {
#pragma unroll
            for (int nt = 0; nt < 8; nt++) {
                const int c0 = nt*8 + 2*(lane & 3);
                if (c0     > r0)     s[nt][0] = -1e9f;
                if (c0 + 1 > r0)     s[nt][1] = -1e9f;
                if (c0     > r0 + 8) s[nt][2] = -1e9f;
                if (c0 + 1 > r0 + 8) s[nt][3] = -1e9f;
            }
        }

        float mx0 = -1e30f, mx1 = -1e30f;
#pragma unroll
        for (int nt = 0; nt < 8; nt++) {
            mx0 = fmaxf(mx0, fmaxf(s[nt][0], s[nt][1]));
            mx1 = fmaxf(mx1, fmaxf(s[nt][2], s[nt][3]));
        }
        mx0 = fmaxf(mx0, __shfl_xor_sync(0xffffffffu, mx0, 1));
        mx0 = fmaxf(mx0, __shfl_xor_sync(0xffffffffu, mx0, 2));
        mx1 = fmaxf(mx1, __shfl_xor_sync(0xffffffffu, mx1, 1));
        mx1 = fmaxf(mx1, __shfl_xor_sync(0xffffffffu, mx1, 2));

        const float mn0 = fmaxf(m0r, mx0);
        const float mn1 = fmaxf(m1r, mx1);
        const float sc0 = __expf(m0r - mn0);
        const float sc1 = __expf(m1r - mn1);
        m0r = mn0; m1r = mn1;

        float rs0 = 0.f, rs1 = 0.f;
#pragma unroll
        for (int nt = 0; nt < 8; nt++) {
            s[nt][0] = __expf(s[nt][0] - mn0); rs0 += s[nt][0];
            s[nt][1] = __expf(s[nt][1] - mn0); rs0 += s[nt][1];
            s[nt][2] = __expf(s[nt][2] - mn1); rs1 += s[nt][2];
            s[nt][3] = __expf(s[nt][3] - mn1); rs1 += s[nt][3];
        }
        rs0 += __shfl_xor_sync(0xffffffffu, rs0, 1);
        rs0 += __shfl_xor_sync(0xffffffffu, rs0, 2);
        rs1 += __shfl_xor_sync(0xffffffffu, rs1, 1);
        rs1 += __shfl_xor_sync(0xffffffffu, rs1, 2);
        l0r = l0r*sc0 + rs0;
        l1r = l1r*sc1 + rs1;

#pragma unroll
        for (int nt = 0; nt < 16; nt++) {
            o[nt][0] *= sc0; o[nt][1] *= sc0;
            o[nt][2] *= sc1; o[nt][3] *= sc1;
        }

        // ---- O += P V : Ph*Vh only ----
#pragma unroll
        for (int kc4 = 0; kc4 < 4; kc4++) {
            uint32_t aPh[4];
#pragma unroll
            for (int hh = 0; hh < 2; hh++) {
                aPh[2*hh]   = pack_f16x2(s[2*kc4+hh][0], s[2*kc4+hh][1]);
                aPh[2*hh+1] = pack_f16x2(s[2*kc4+hh][2], s[2*kc4+hh][3]);
            }
#pragma unroll
            for (int ntp = 0; ntp < 8; ntp++) {
                uint32_t vH[4];
                const uint32_t vo = voff4 + (uint32_t)(kc4*(16*FSTR*2)) + ntp*32;
                ldmat4t(vH, aVh + vo);
                mma16816(o[2*ntp],   aPh, vH[0], vH[1]);
                mma16816(o[2*ntp+1], aPh, vH[2], vH[3]);
            }
        }
    }

    const float li0 = 1.f / l0r, li1 = 1.f / l1r;
    const int rg = q0 + r0;
    const int cb = 2*(lane & 3);
#pragma unroll
    for (int nt = 0; nt < 16; nt++) {
        const int col = nt*8 + cb;
        *(float2*)&out[base + (size_t)rg*H_ + col] =
            make_float2(o[nt][0]*li0, o[nt][1]*li0);
        *(float2*)&out[base + (size_t)(rg+8)*H_ + col] =
            make_float2(o[nt][2]*li1, o[nt][3]*li1);
    }
}

// ---------------------------------------------------------------------------
extern "C" void kernel_launch(void* const* d_in, const int* in_sizes, int n_in,
                              void* d_out, int out_size)
{
    (void)in_sizes; (void)n_in; (void)out_size;
    const float* x  = (const float*)d_in[0];
    const float* Wq = (const float*)d_in[1];
    const float* Wk = (const float*)d_in[2];
    const float* Wv = (const float*)d_in[3];
    float* out = (float*)d_out;

    convert_w_kernel<<<dim3((D_*H_)/256, 3), 256>>>(Wq, Wk, Wv);

    cudaFuncSetAttribute(proj_hmma3_kernel,
                         cudaFuncAttributeMaxDynamicSharedMemorySize, PX_SMEM);
    proj_hmma3_kernel<<<M_/128, 256, PX_SMEM>>>(x);

    cudaFuncSetAttribute(flash5_kernel,
                         cudaFuncAttributeMaxDynamicSharedMemorySize, FSMEM);
    flash5_kernel<<<dim3(16, B_), 256, FSMEM>>>(out);
}

// round 15
// speedup vs baseline: 5.2039x; 1.1153x over previous
#include <cuda_runtime.h>
#include <cuda_fp16.h>
#include <math.h>
#include <stdint.h>

#define B_ 8
#define T_ 2048
#define D_ 2048
#define H_ 128
#define M_ (B_*T_)

// Scratch (alloc-free rules: __device__ globals)
__device__ __half g_qhi[M_*H_], g_qlo[M_*H_];   // q pre-scaled by sqrt(128)
__device__ __half g_khi[M_*H_], g_klo[M_*H_];
__device__ __half g_vhi[M_*H_];                 // v: plain fp16
__device__ __half g_wthi[3][H_*D_];             // W^T: [n][k], weight-major
__device__ __half g_wtlo[3][H_*D_];

// ---------------------------------------------------------------------------
// helpers
// ---------------------------------------------------------------------------
__device__ __forceinline__ uint32_t smem_u32(const void* p) {
    uint32_t a;
    asm("{ .reg .u64 t; cvta.to.shared.u64 t, %1; cvt.u32.u64 %0, t; }" : "=r"(a) : "l"(p));
    return a;
}
__device__ __forceinline__ void ldmat4(uint32_t* r, uint32_t addr) {
    asm volatile("ldmatrix.sync.aligned.m8n8.x4.shared.b16 {%0,%1,%2,%3}, [%4];"
        : "=r"(r[0]), "=r"(r[1]), "=r"(r[2]), "=r"(r[3]) : "r"(addr));
}
__device__ __forceinline__ void ldmat4t(uint32_t* r, uint32_t addr) {
    asm volatile("ldmatrix.sync.aligned.m8n8.x4.trans.shared.b16 {%0,%1,%2,%3}, [%4];"
        : "=r"(r[0]), "=r"(r[1]), "=r"(r[2]), "=r"(r[3]) : "r"(addr));
}
__device__ __forceinline__ void mma16816(float* d, const uint32_t* a,
                                         uint32_t b0, uint32_t b1) {
    asm volatile(
        "mma.sync.aligned.m16n8k16.row.col.f32.f16.f16.f32 "
        "{%0,%1,%2,%3}, {%4,%5,%6,%7}, {%8,%9}, {%0,%1,%2,%3};"
        : "+f"(d[0]), "+f"(d[1]), "+f"(d[2]), "+f"(d[3])
        : "r"(a[0]), "r"(a[1]), "r"(a[2]), "r"(a[3]), "r"(b0), "r"(b1));
}
__device__ __forceinline__ uint32_t pack_f16x2(float even, float odd) {
    uint32_t r;
    asm("cvt.rn.f16x2.f32 %0, %1, %2;" : "=r"(r) : "f"(odd), "f"(even));
    return r;
}
#define CP_ASYNC16(dst, src) \
    asm volatile("cp.async.cg.shared.global [%0], [%1], 16;" :: "r"(dst), "l"(src))
#define CP_COMMIT() asm volatile("cp.async.commit_group;" ::: "memory")
#define CP_WAIT0()  asm volatile("cp.async.wait_group 0;" ::: "memory")

// ---------------------------------------------------------------------------
// W convert v2: smem tile transpose, coalesced uint4 in and out.
// grid 96 = 3 weights x 32 k-tiles (64 k each). smem [64][133] fp32.
// ---------------------------------------------------------------------------
__global__ __launch_bounds__(256) void convert_w2_kernel(
    const float* __restrict__ Wq, const float* __restrict__ Wk, const float* __restrict__ Wv)
{
    extern __shared__ float cs[];
    const int w  = blockIdx.x >> 5;
    const int kt = blockIdx.x & 31;
    const float* W = (w == 0) ? Wq : (w == 1) ? Wk : Wv;
    const int t  = threadIdx.x;
    const int k0 = kt * 64;

    // load 64x128 fp32 tile (coalesced float4), store scalar to stride-133 smem
#pragma unroll
    for (int i = 0; i < 8; i++) {
        const int idx = t + i*256;
        const int r = idx >> 5, c4 = idx & 31;
        float4 v = *(const float4*)(W + (size_t)(k0 + r) * H_ + c4*4);
        float* d = &cs[r*133 + c4*4];
        d[0] = v.x; d[1] = v.y; d[2] = v.z; d[3] = v.w;
    }
    __syncthreads();

    // transpose out: thread = (n = t>>1, k-half = t&1), 32 k each, uint4 stores
    const int n  = t >> 1;
    const int jh = t & 1;
#pragma unroll
    for (int jb = 0; jb < 4; jb++) {
        float v[8];
#pragma unroll
        for (int u = 0; u < 8; u++)
            v[u] = cs[(jh*32 + jb*8 + u)*133 + n];
        uint32_t hw[4], lw[4];
#pragma unroll
        for (int j = 0; j < 4; j++) {
            hw[j] = pack_f16x2(v[2*j], v[2*j+1]);
            __half2 hh = *(const __half2*)&hw[j];
            lw[j] = pack_f16x2(v[2*j]   - __half2float(hh.x),
                               v[2*j+1] - __half2float(hh.y));
        }
        const size_t o = (size_t)n * D_ + k0 + jh*32 + jb*8;
        *(uint4*)(&g_wthi[w][o]) = make_uint4(hw[0], hw[1], hw[2], hw[3]);
        *(uint4*)(&g_wtlo[w][o]) = make_uint4(lw[0], lw[1], lw[2], lw[3]);
    }
}

// ---------------------------------------------------------------------------
// Projection v4: grid 148 (136 CTAs x 7 m-frags + 12 x 6), N = 384 (all 3 W).
// Warp layout 1(M) x 8(N): warp covers 48 cols. fp16 splits:
//   q,k cols (<256): hh + hl + lh.   v cols (>=256): hh only.
// ---------------------------------------------------------------------------
#define PX_RAW(buf) ((buf)*16128u)                  // 112 x 144B fp32 raw A
#define PX_AHI(buf) (32256u + (buf)*17920u)         // 112x40 f16 (stride 80B)
#define PX_ALO(buf) (PX_AHI(buf) + 8960u)
#define PX_BHI(buf) (68096u + (buf)*61440u)         // 384x40 f16 (stride 80B)
#define PX_BLO(buf) (PX_BHI(buf) + 30720u)
#define PX_SMEM     190976

template<int NF>
__device__ __forceinline__ void proj_core(
    const float* __restrict__ x, char* psm, uint32_t s0,
    int t, int lane, int wid, int m0)
{
    const __half* WT_hi = &g_wthi[0][0];
    const __half* WT_lo = &g_wtlo[0][0];

    float acc[NF][6][4];
#pragma unroll
    for (int mt = 0; mt < NF; mt++)
#pragma unroll
        for (int nt = 0; nt < 6; nt++)
#pragma unroll
            for (int e = 0; e < 4; e++) acc[mt][nt][e] = 0.f;

    const int arow = t >> 1;                 // A cp.async: 2 thr/row (row < NF*16)
    const int ac0  = (t & 1) * 4;

    // ldmatrix address components (proven formulas; warp col base = wid*48)
    const uint32_t aoff = (uint32_t)((((lane & 15))*40 + (lane >> 4)*8) * 2);
    const uint32_t boff = (uint32_t)(((wid*48 + (lane & 7) + ((lane >> 4) & 1)*8)*40
                                      + ((lane >> 3) & 1)*8) * 2);

    // prologue: issue chunk 0
    {
#pragma unroll
        for (int i = 0; i < 4; i++) {
            const int idx = t + i*256;
            if (idx < NF*128) {
                const int row = idx >> 3, c = idx & 7;
                CP_ASYNC16(s0 + PX_RAW(0) + (uint32_t)(row*144 + c*16),
                           x + (size_t)(m0 + row) * D_ + c*4);
            }
        }
#pragma unroll
        for (int i = 0; i < 6; i++) {
            const int idx = t + i*256;
            const int n = idx >> 2, c = idx & 3;
            CP_ASYNC16(s0 + PX_BHI(0) + (uint32_t)(n*80 + c*16),
                       WT_hi + (size_t)n * D_ + c*8);
            CP_ASYNC16(s0 + PX_BLO(0) + (uint32_t)(n*80 + c*16),
                       WT_lo + (size_t)n * D_ + c*8);
        }
        CP_COMMIT();
    }

    for (int ch = 0; ch < 64; ch++) {
        const int buf = ch & 1;

        CP_WAIT0();
        __syncthreads();

        // convert A raw fp32 -> f16 hi/lo (rows < NF*16)
        if (t < NF*32) {
            const int row = t >> 1, half = t & 1;
            const char* rsrc = psm + PX_RAW(buf) + row*144 + half*64;
            char* dhi = psm + PX_AHI(buf) + (row*40 + half*16)*2;
            char* dlo = psm + PX_ALO(buf) + (row*40 + half*16)*2;
#pragma unroll
            for (int j = 0; j < 4; j++) {
                float4 v = *(const float4*)(rsrc + j*16);
                uint32_t h01 = pack_f16x2(v.x, v.y);
                uint32_t h23 = pack_f16x2(v.z, v.w);
                __half2 b01 = *(const __half2*)&h01;
                __half2 b23 = *(const __half2*)&h23;
                uint32_t l01 = pack_f16x2(v.x - __half2float(b01.x),
                                          v.y - __half2float(b01.y));
                uint32_t l23 = pack_f16x2(v.z - __half2float(b23.x),
                                          v.w - __half2float(b23.y));
                *(uint32_t*)(dhi + j*8)     = h01;
                *(uint32_t*)(dhi + j*8 + 4) = h23;
                *(uint32_t*)(dlo + j*8)     = l01;
                *(uint32_t*)(dlo + j*8 + 4) = l23;
            }
        }
        __syncthreads();

        // issue chunk ch+1 (interleaves with MMA)
        if (ch < 63) {
            const int nbuf = buf ^ 1;
            const int k0 = (ch + 1) * 32;
#pragma unroll
            for (int i = 0; i < 4; i++) {
                const int idx = t + i*256;
                if (idx < NF*128) {
                    const int row = idx >> 3, c = idx & 7;
                    CP_ASYNC16(s0 + PX_RAW(nbuf) + (uint32_t)(row*144 + c*16),
                               x + (size_t)(m0 + row) * D_ + k0 + c*4);
                }
            }
#pragma unroll
            for (int i = 0; i < 6; i++) {
                const int idx = t + i*256;
                const int n = idx >> 2, c = idx & 3;
                CP_ASYNC16(s0 + PX_BHI(nbuf) + (uint32_t)(n*80 + c*16),
                           WT_hi + (size_t)n * D_ + k0 + c*8);
                CP_ASYNC16(s0 + PX_BLO(nbuf) + (uint32_t)(n*80 + c*16),
                           WT_lo + (size_t)n * D_ + k0 + c*8);
            }
            CP_COMMIT();
        }

        // compute chunk ch
#pragma unroll
        for (int ks = 0; ks < 2; ks++) {
            const uint32_t abh = s0 + PX_AHI(buf) + aoff + ks*32;
            const uint32_t abl = s0 + PX_ALO(buf) + aoff + ks*32;
            const uint32_t bbh = s0 + PX_BHI(buf) + boff + ks*32;
            const uint32_t bbl = s0 + PX_BLO(buf) + boff + ks*32;

            uint32_t a[NF][4], bh[3][4];
#pragma unroll
            for (int mt = 0; mt < NF; mt++)
                ldmat4(a[mt], abh + (uint32_t)(mt*1280));
#pragma unroll
            for (int np = 0; np < 3; np++) {
                ldmat4(bh[np], bbh + (uint32_t)(np*1280));
#pragma unroll
                for (int mt = 0; mt < NF; mt++) {
                    mma16816(acc[mt][2*np],   a[mt], bh[np][0], bh[np][1]);
                    mma16816(acc[mt][2*np+1], a[mt], bh[np][2], bh[np][3]);
                }
                if (wid*48 + np*16 < 256) {          // q,k cols: hl term
                    uint32_t bl[4];
                    ldmat4(bl, bbl + (uint32_t)(np*1280));
#pragma unroll
                    for (int mt = 0; mt < NF; mt++) {
                        mma16816(acc[mt][2*np],   a[mt], bl[0], bl[1]);
                        mma16816(acc[mt][2*np+1], a[mt], bl[2], bl[3]);
                    }
                }
            }
            // lh pass: A = lo, q,k cols only (bh kept in regs)
            if (wid*48 < 256) {
#pragma unroll
                for (int mt = 0; mt < NF; mt++)
                    ldmat4(a[mt], abl + (uint32_t)(mt*1280));
#pragma unroll
                for (int np = 0; np < 3; np++) {
                    if (wid*48 + np*16 < 256) {
#pragma unroll
                        for (int mt = 0; mt < NF; mt++) {
                            mma16816(acc[mt][2*np],   a[mt], bh[np][0], bh[np][1]);
                            mma16816(acc[mt][2*np+1], a[mt], bh[np][2], bh[np][3]);
                        }
                    }
                }
            }
        }
    }

    // epilogue: q,k -> f16 hi/lo (q scaled by sqrt(128)); v -> f16 hi only
    const int dr = lane >> 2;
    const int dc = (lane & 3) * 2;
#pragma unroll
    for (int mt = 0; mt < NF; mt++) {
#pragma unroll
        for (int nt = 0; nt < 6; nt++) {
            const int cg  = wid*48 + nt*8 + dc;
            const int w   = cg >> 7;
            const int col = cg & 127;
            const int row = m0 + mt*16 + dr;
            if (w == 2) {
#pragma unroll
                for (int half = 0; half < 2; half++) {
                    const int rr = row + half*8;
                    uint32_t h = pack_f16x2(acc[mt][nt][half*2 + 0],
                                            acc[mt][nt][half*2 + 1]);
                    *(uint32_t*)(g_vhi + (size_t)rr * H_ + col) = h;
                }
            } else {
                __half* ohi = (w == 0) ? g_qhi : g_khi;
                __half* olo = (w == 0) ? g_qlo : g_klo;
                const float sc = (w == 0) ? 11.313708498984761f : 1.0f;
#pragma unroll
                for (int half = 0; half < 2; half++) {
                    const int rr = row + half*8;
                    float v0 = acc[mt][nt][half*2 + 0] * sc;
                    float v1 = acc[mt][nt][half*2 + 1] * sc;
                    uint32_t h = pack_f16x2(v0, v1);
                    __half2 bh2 = *(const __half2*)&h;
                    uint32_t l = pack_f16x2(v0 - __half2float(bh2.x),
                                            v1 - __half2float(bh2.y));
                    *(uint32_t*)(ohi + (size_t)rr * H_ + col) = h;
                    *(uint32_t*)(olo + (size_t)rr * H_ + col) = l;
                }
            }
        }
    }
}

__global__ __launch_bounds__(256, 1) void proj_hmma4_kernel(const float* __restrict__ x)
{
    extern __shared__ char psm[];
    const uint32_t s0 = smem_u32(psm);
    const int t    = threadIdx.x;
    const int lane = t & 31;
    const int wid  = t >> 5;
    const int bid  = blockIdx.x;

    if (bid < 136) {
        proj_core<7>(x, psm, s0, t, lane, wid, bid*112);
    } else {
        proj_core<6>(x, psm, s0, t, lane, wid, 15232 + (bid-136)*96);
    }
}

// ---------------------------------------------------------------------------
// Flash attention v5 (unchanged — at HMMA floor)
// ---------------------------------------------------------------------------
#define FSTR 136
#define FQH  (64*FSTR)
#define FGRP (5*FQH)
#define FSMEM (2*FGRP*2)

__global__ __launch_bounds__(256) void flash5_kernel(float* __restrict__ out)
{
    extern __shared__ __half fsm[];
    const int t    = threadIdx.x;
    const int g    = t >> 7;
    const int gt   = t & 127;
    const int warp = gt >> 5;
    const int lane = t & 31;
    const int b    = blockIdx.y;
    const int p    = blockIdx.x;
    const int qb   = g ? p : (31 - p);
    const int q0   = qb * 64;
    const size_t base = (size_t)b * T_ * H_;

    __half* sQh = fsm + g*FGRP;
    __half* sQl = sQh + FQH;
    __half* sKh = sQl + FQH;
    __half* sKl = sKh + FQH;
    __half* sVh = sKl + FQH;
    const uint32_t aQh = smem_u32(sQh), aQl = smem_u32(sQl);
    const uint32_t aKh = smem_u32(sKh), aKl = smem_u32(sKl);
    const uint32_t aVh = smem_u32(sVh);

#pragma unroll
    for (int i = 0; i < 8; i++) {
        const int idx = gt + i*128;
        const int row = idx >> 4, c = idx & 15;
        const size_t go = base + (size_t)(q0 + row)*H_ + c*8;
        *(uint4*)(sQh + row*FSTR + c*8) = *(const uint4*)(g_qhi + go);
        *(uint4*)(sQl + row*FSTR + c*8) = *(const uint4*)(g_qlo + go);
    }

    float o[16][4];
#pragma unroll
    for (int nt = 0; nt < 16; nt++)
#pragma unroll
        for (int e = 0; e < 4; e++) o[nt][e] = 0.f;
    float m0r = -1e30f, m1r = -1e30f, l0r = 0.f, l1r = 0.f;

    const uint32_t aoff = (uint32_t)(((warp*16 + (lane & 15))*FSTR + (lane >> 4)*8) * 2);
    const uint32_t boff = (uint32_t)((((lane & 7) + ((lane >> 4) & 1)*8)*FSTR
                                      + ((lane >> 3) & 1)*8) * 2);
    const uint32_t voff4 = (uint32_t)(((lane & 15)*FSTR)*2 + (lane >> 4)*16);

    const int r0 = warp*16 + (lane >> 2);

    for (int kb = 0; kb <= qb; kb++) {
        const int k0 = kb * 64;
        asm volatile("bar.sync %0, %1;" :: "r"(g+1), "r"(128) : "memory");

#pragma unroll
        for (int i = 0; i < 8; i++) {
            const int idx = gt + i*128;
            const int row = idx >> 4, c = idx & 15;
            const size_t go = base + (size_t)(k0 + row)*H_ + c*8;
            *(uint4*)(sKh + row*FSTR + c*8) = *(const uint4*)(g_khi + go);
            *(uint4*)(sKl + row*FSTR + c*8) = *(const uint4*)(g_klo + go);
            *(uint4*)(sVh + row*FSTR + c*8) = *(const uint4*)(g_vhi + go);
        }
        asm volatile("bar.sync %0, %1;" :: "r"(g+1), "r"(128) : "memory");

        // ---- S = Q K^T : hh + hl + lh ----
        float s[8][4];
#pragma unroll
        for (int nt = 0; nt < 8; nt++)
#pragma unroll
            for (int e = 0; e < 4; e++) s[nt][e] = 0.f;

#pragma unroll
        for (int kc = 0; kc < 8; kc++) {
            uint32_t aH[4], aL[4];
            ldmat4(aH, aQh + aoff + kc*32);
            ldmat4(aL, aQl + aoff + kc*32);
#pragma unroll
            for (int ntp = 0; ntp < 4; ntp++) {
                uint32_t bH[4], bL[4];
                const uint32_t bo = boff + (uint32_t)(ntp*(16*FSTR*2)) + kc*32;
                ldmat4(bH, aKh + bo);
                ldmat4(bL, aKl + bo);
#pragma unroll
                for (int h = 0; h < 2; h++) {
                    const int nt = ntp*2 + h;
                    mma16816(s[nt], aH, bH[2*h], bH[2*h+1]);
                    mma16816(s[nt], aH, bL[2*h], bL[2*h+1]);
                    mma16816(s[nt], aL, bH[2*h], bH[2*h+1]);
                }
            }
        }

        if (kb == qb) {
#pragma unroll
            for (int nt = 0; nt < 8; nt++) {
                const int c0 = nt*8 + 2*(lane & 3);
                if (c0     > r0)     s[nt][0] = -1e9f;
                if (c0 + 1 > r0)     s[nt][1] = -1e9f;
                if (c0     > r0 + 8) s[nt][2] = -1e9f;
                if (c0 + 1 > r0 + 8) s[nt][3] = -1e9f;
            }
        }

        float mx0 = -1e30f, mx1 = -1e30f;
#pragma unroll
        for (int nt = 0; nt < 8; nt++) {
            mx0 = fmaxf(mx0, fmaxf(s[nt][0], s[nt][1]));
            mx1 = fmaxf(mx1, fmaxf(s[nt][2], s[nt][3]));
        }
        mx0 = fmaxf(mx0, __shfl_xor_sync(0xffffffffu, mx0, 1));
        mx0 = fmaxf(mx0, __shfl_xor_sync(0xffffffffu, mx0, 2));
        mx1 = fmaxf(mx1, __shfl_xor_sync(0xffffffffu, mx1, 1));
        mx1 = fmaxf(mx1, __shfl_xor_sync(0xffffffffu, mx1, 2));

        const float mn0 = fmaxf(m0r, mx0);
        const float mn1 = fmaxf(m1r, mx1);
        const float sc0 = __expf(m0r - mn0);
        const float sc1 = __expf(m1r - mn1);
        m0r = mn0; m1r = mn1;

        float rs0 = 0.f, rs1 = 0.f;
#pragma unroll
        for (int nt = 0; nt < 8; nt++) {
            s[nt][0] = __expf(s[nt][0] - mn0); rs0 += s[nt][0];
            s[nt][1] = __expf(s[nt][1] - mn0); rs0 += s[nt][1];
            s[nt][2] = __expf(s[nt][2] - mn1); rs1 += s[nt][2];
            s[nt][3] = __expf(s[nt][3] - mn1); rs1 += s[nt][3];
        }
        rs0 += __shfl_xor_sync(0xffffffffu, rs0, 1);
        rs0 += __shfl_xor_sync(0xffffffffu, rs0, 2);
        rs1 += __shfl_xor_sync(0xffffffffu, rs1, 1);
        rs1 += __shfl_xor_sync(0xffffffffu, rs1, 2);
        l0r = l0r*sc0 + rs0;
        l1r = l1r*sc1 + rs1;

#pragma unroll
        for (int nt = 0; nt < 16; nt++) {
            o[nt][0] *= sc0; o[nt][1] *= sc0;
            o[nt][2] *= sc1; o[nt][3] *= sc1;
        }

        // ---- O += P V : Ph*Vh only ----
#pragma unroll
        for (int kc4 = 0; kc4 < 4; kc4++) {
            uint32_t aPh[4];
#pragma unroll
            for (int hh = 0; hh < 2; hh++) {
                aPh[2*hh]   = pack_f16x2(s[2*kc4+hh][0], s[2*kc4+hh][1]);
                aPh[2*hh+1] = pack_f16x2(s[2*kc4+hh][2], s[2*kc4+hh][3]);
            }
#pragma unroll
            for (int ntp = 0; ntp < 8; ntp++) {
                uint32_t vH[4];
                const uint32_t vo = voff4 + (uint32_t)(kc4*(16*FSTR*2)) + ntp*32;
                ldmat4t(vH, aVh + vo);
                mma16816(o[2*ntp],   aPh, vH[0], vH[1]);
                mma16816(o[2*ntp+1], aPh, vH[2], vH[3]);
            }
        }
    }

    const float li0 = 1.f / l0r, li1 = 1.f / l1r;
    const int rg = q0 + r0;
    const int cb = 2*(lane & 3);
#pragma unroll
    for (int nt = 0; nt < 16; nt++) {
        const int col = nt*8 + cb;
        *(float2*)&out[base + (size_t)rg*H_ + col] =
            make_float2(o[nt][0]*li0, o[nt][1]*li0);
        *(float2*)&out[base + (size_t)(rg+8)*H_ + col] =
            make_float2(o[nt][2]*li1, o[nt][3]*li1);
    }
}

// ---------------------------------------------------------------------------
extern "C" void kernel_launch(void* const* d_in, const int* in_sizes, int n_in,
                              void* d_out, int out_size)
{
    (void)in_sizes; (void)n_in; (void)out_size;
    const float* x  = (const float*)d_in[0];
    const float* Wq = (const float*)d_in[1];
    const float* Wk = (const float*)d_in[2];
    const float* Wv = (const float*)d_in[3];
    float* out = (float*)d_out;

    convert_w2_kernel<<<96, 256, 64*133*4>>>(Wq, Wk, Wv);

    cudaFuncSetAttribute(proj_hmma4_kernel,
                         cudaFuncAttributeMaxDynamicSharedMemorySize, PX_SMEM);
    proj_hmma4_kernel<<<148, 256, PX_SMEM>>>(x);

    cudaFuncSetAttribute(flash5_kernel,
                         cudaFuncAttributeMaxDynamicSharedMemorySize, FSMEM);
    flash5_kernel<<<dim3(16, B_), 256, FSMEM>>>(out);
}